// round 6
// baseline (speedup 1.0000x reference)
#include <cuda_runtime.h>
#include <cstdint>

#define D_IN  128
#define D_HID 48
#define D_OUT 32
#define MAX_N 100000
#define MAX_E 1600000
#define NB_MAX 512

// Scratch (module-static device memory — sanctioned no-alloc pattern)
__device__ float s_h1 [MAX_N * D_HID];
__device__ float s_a1 [MAX_N * D_HID];
__device__ float s_h2 [MAX_N * D_OUT];
__device__ float s_deg[MAX_N];
__device__ int   s_cnt[MAX_N];
__device__ int   s_ex [MAX_N];
__device__ int   s_row[MAX_N + 1];
__device__ int   s_cur[MAX_N];
__device__ int   s_bsum[NB_MAX];
__device__ int   s_src[MAX_E];
__device__ int   s_dst[MAX_E];
__device__ int   s_col[MAX_E];
__device__ float s_val[MAX_E];
__device__ int   s_flag[1];

// ---------------------------------------------------------------------------
// Launch 1: zero counters + detect edge_index dtype
// ---------------------------------------------------------------------------
__global__ void gcn_zero_detect(const unsigned* __restrict__ ei_words,
                                float* __restrict__ deg, int* __restrict__ cnt,
                                int* __restrict__ flag, int n) {
    int stride = gridDim.x * blockDim.x;
    for (int i = blockIdx.x * blockDim.x + threadIdx.x; i < n; i += stride) {
        deg[i] = 0.f; cnt[i] = 0;
    }
    if (blockIdx.x == 0 && threadIdx.x == 0) {
        int nz = 0;
        #pragma unroll 8
        for (int i = 1; i < 512; i += 2) nz += (ei_words[i] != 0u);
        flag[0] = (nz == 0) ? 1 : 0;   // int64 => odd words all zero
    }
}

// ---------------------------------------------------------------------------
// Launch 2: convert indices (clamped) + weighted degree + in-degree count
// ---------------------------------------------------------------------------
__global__ void gcn_prep(const void* __restrict__ ei_raw,
                         const float* __restrict__ ew,
                         const int* __restrict__ flag,
                         float* __restrict__ deg, int* __restrict__ cnt,
                         int* __restrict__ src32, int* __restrict__ dst32,
                         int n, int E) {
    int stride = gridDim.x * blockDim.x;
    bool is64 = (flag[0] != 0);
    const long long* ei64 = (const long long*)ei_raw;
    const int*       ei32 = (const int*)ei_raw;
    for (int e = blockIdx.x * blockDim.x + threadIdx.x; e < E; e += stride) {
        int sv, dv;
        if (is64) { sv = (int)ei64[e]; dv = (int)ei64[E + e]; }
        else      { sv = ei32[e];      dv = ei32[E + e]; }
        sv = min(max(sv, 0), n - 1);
        dv = min(max(dv, 0), n - 1);
        src32[e] = sv;
        dst32[e] = dv;
        atomicAdd(deg + dv, ew[e]);
        atomicAdd(cnt + dv, 1);
    }
}

// ---------------------------------------------------------------------------
// Launch 3: per-block scan of cnt (+ fused dinv = rsqrt(deg+1))
// ---------------------------------------------------------------------------
__global__ void scan_blocks(const int* __restrict__ cnt,
                            int* __restrict__ ex, int* __restrict__ bsum,
                            float* __restrict__ deg, int n) {
    __shared__ int sh[256];
    int i = blockIdx.x * 256 + threadIdx.x;
    if (i < n) deg[i] = rsqrtf(deg[i] + 1.0f);   // self-loop weight 1
    int v = (i < n) ? cnt[i] : 0;
    sh[threadIdx.x] = v;
    __syncthreads();
    #pragma unroll
    for (int off = 1; off < 256; off <<= 1) {
        int t = (threadIdx.x >= off) ? sh[threadIdx.x - off] : 0;
        __syncthreads();
        sh[threadIdx.x] += t;
        __syncthreads();
    }
    if (i < n) ex[i] = sh[threadIdx.x] - v;
    if (threadIdx.x == 255) bsum[blockIdx.x] = sh[255];
}

// Launch 4
__global__ void scan_bsums(int* __restrict__ bsum, int nb) {
    __shared__ int sh[NB_MAX];
    int v = (threadIdx.x < nb) ? bsum[threadIdx.x] : 0;
    sh[threadIdx.x] = v;
    __syncthreads();
    #pragma unroll
    for (int off = 1; off < NB_MAX; off <<= 1) {
        int t = (threadIdx.x >= off) ? sh[threadIdx.x - off] : 0;
        __syncthreads();
        sh[threadIdx.x] += t;
        __syncthreads();
    }
    if (threadIdx.x < nb) bsum[threadIdx.x] = sh[threadIdx.x] - v;
}

// Launch 5
__global__ void scan_add(const int* __restrict__ ex, const int* __restrict__ bsum,
                         int* __restrict__ rowptr, int* __restrict__ cursor,
                         int n, int E) {
    int i = blockIdx.x * 256 + threadIdx.x;
    if (i < n) {
        int r = ex[i] + bsum[blockIdx.x];
        rowptr[i] = r;
        cursor[i] = r;
    }
    if (i == 0) rowptr[n] = E;
}

// ---------------------------------------------------------------------------
// Launch 6: K-tiled fp32 GEMM (float4 global loads)  — ncu -s 5 lands HERE
// ---------------------------------------------------------------------------
template<int DIN, int DOUT, int BM, int BK, int TM, int TN>
__global__ void gcn_gemm(const float* __restrict__ X,
                         const float* __restrict__ W,
                         float* __restrict__ H, int n) {
    constexpr int RT = BM / TM;
    constexpr int CT = DOUT / TN;
    constexpr int NT = RT * CT;

    __shared__ float sXT[BK * (BM + 1)];
    __shared__ float sW [BK * DOUT];

    int tid  = threadIdx.x;
    int row0 = blockIdx.x * BM;
    int ti = tid / CT;
    int tj = tid % CT;

    float acc[TM][TN];
    #pragma unroll
    for (int i = 0; i < TM; i++)
        #pragma unroll
        for (int j = 0; j < TN; j++) acc[i][j] = 0.f;

    for (int k0 = 0; k0 < DIN; k0 += BK) {
        // X tile: float4 loads, transposed scatter into padded smem
        for (int i = tid; i < BM * (BK / 4); i += NT) {
            int r  = i / (BK / 4);
            int c4 = i % (BK / 4);
            float4 v = make_float4(0.f, 0.f, 0.f, 0.f);
            if (row0 + r < n)
                v = *(const float4*)(X + (size_t)(row0 + r) * DIN + k0 + 4 * c4);
            sXT[(4 * c4 + 0) * (BM + 1) + r] = v.x;
            sXT[(4 * c4 + 1) * (BM + 1) + r] = v.y;
            sXT[(4 * c4 + 2) * (BM + 1) + r] = v.z;
            sXT[(4 * c4 + 3) * (BM + 1) + r] = v.w;
        }
        // W tile: float4 loads
        for (int i = tid; i < BK * (DOUT / 4); i += NT) {
            int kk = i / (DOUT / 4);
            int c4 = i % (DOUT / 4);
            float4 v = *(const float4*)(W + (size_t)(k0 + kk) * DOUT + 4 * c4);
            *(float4*)(sW + kk * DOUT + 4 * c4) = v;
        }
        __syncthreads();

        #pragma unroll 4
        for (int kk = 0; kk < BK; kk++) {
            float xr[TM];
            #pragma unroll
            for (int i = 0; i < TM; i++) xr[i] = sXT[kk * (BM + 1) + ti * TM + i];
            #pragma unroll
            for (int j = 0; j < TN; j++) {
                float wv = sW[kk * DOUT + tj * TN + j];
                #pragma unroll
                for (int i = 0; i < TM; i++) acc[i][j] += xr[i] * wv;
            }
        }
        __syncthreads();
    }

    #pragma unroll
    for (int i = 0; i < TM; i++) {
        int r = row0 + ti * TM + i;
        if (r < n) {
            #pragma unroll
            for (int j = 0; j < TN; j++)
                H[(size_t)r * DOUT + tj * TN + j] = acc[i][j];
        }
    }
}

// ---------------------------------------------------------------------------
// Launch 7: CSR build
// ---------------------------------------------------------------------------
__global__ void gcn_build(const int* __restrict__ src32,
                          const int* __restrict__ dst32,
                          const float* __restrict__ ew,
                          const float* __restrict__ dinv,
                          int* __restrict__ cursor,
                          int* __restrict__ col, float* __restrict__ val, int E) {
    int e = blockIdx.x * blockDim.x + threadIdx.x;
    if (e >= E) return;
    int d = dst32[e];
    int pos = atomicAdd(cursor + d, 1);
    int s = src32[e];
    col[pos] = s;
    val[pos] = dinv[s] * ew[e];
}

// ---------------------------------------------------------------------------
// CSR aggregation: warp per node, float2 lanes (L = D/2 active), 4-edge unroll
// with 4 independent accumulators (MLP=4). Fused self-loop + bias (+ relu).
// ---------------------------------------------------------------------------
template<int D, bool RELU>
__global__ void gcn_agg(const int* __restrict__ rowptr,
                        const int* __restrict__ col,
                        const float* __restrict__ val,
                        const float* __restrict__ h,
                        const float* __restrict__ dinv,
                        const float* __restrict__ b,
                        float* __restrict__ out, int n) {
    constexpr int L = D / 2;                 // active float2 lanes
    int warp = (blockIdx.x * blockDim.x + threadIdx.x) >> 5;
    int lane = threadIdx.x & 31;
    if (warp >= n) return;

    int r0 = rowptr[warp];
    int r1 = rowptr[warp + 1];
    bool act = lane < L;

    const float2* h2 = (const float2*)h;
    float2 a0 = {0.f, 0.f}, a1 = {0.f, 0.f}, a2 = {0.f, 0.f}, a3 = {0.f, 0.f};

    int idx = r0;
    for (; idx + 3 < r1; idx += 4) {
        int   c0 = col[idx],     c1 = col[idx + 1];
        int   c2 = col[idx + 2], c3 = col[idx + 3];
        float w0 = val[idx],     w1 = val[idx + 1];
        float w2 = val[idx + 2], w3 = val[idx + 3];
        if (act) {
            float2 v0 = h2[(size_t)c0 * L + lane];
            float2 v1 = h2[(size_t)c1 * L + lane];
            float2 v2 = h2[(size_t)c2 * L + lane];
            float2 v3 = h2[(size_t)c3 * L + lane];
            a0.x += w0 * v0.x; a0.y += w0 * v0.y;
            a1.x += w1 * v1.x; a1.y += w1 * v1.y;
            a2.x += w2 * v2.x; a2.y += w2 * v2.y;
            a3.x += w3 * v3.x; a3.y += w3 * v3.y;
        }
    }
    for (; idx < r1; idx++) {
        int   c = col[idx];
        float w = val[idx];
        if (act) {
            float2 v = h2[(size_t)c * L + lane];
            a0.x += w * v.x; a0.y += w * v.y;
        }
    }

    if (act) {
        float2 A;
        A.x = (a0.x + a1.x) + (a2.x + a3.x);
        A.y = (a0.y + a1.y) + (a2.y + a3.y);

        float di = dinv[warp];
        float2 hv = h2[(size_t)warp * L + lane];
        float2 bb = ((const float2*)b)[lane];
        float2 o;
        o.x = di * A.x + di * di * hv.x + bb.x;
        o.y = di * A.y + di * di * hv.y + bb.y;
        if (RELU) { o.x = fmaxf(o.x, 0.f); o.y = fmaxf(o.y, 0.f); }
        ((float2*)out)[(size_t)warp * L + lane] = o;
    }
}

// ---------------------------------------------------------------------------
extern "C" void kernel_launch(void* const* d_in, const int* in_sizes, int n_in,
                              void* d_out, int out_size) {
    const float* x  = (const float*)d_in[0];
    const void*  ei = d_in[1];
    const float* ew = (const float*)d_in[2];
    const float* W1 = (const float*)d_in[3];
    const float* b1 = (const float*)d_in[4];
    const float* W2 = (const float*)d_in[5];
    const float* b2 = (const float*)d_in[6];
    float*       out = (float*)d_out;

    int n = in_sizes[0] / D_IN;      // 100000
    int E = in_sizes[2];             // 1600000
    int nb = (n + 255) / 256;

    float *h1, *a1, *h2, *deg, *val;
    int *cnt, *ex, *row, *cur, *bsum, *src32, *dst32, *colp, *flag;
    cudaGetSymbolAddress((void**)&h1,    s_h1);
    cudaGetSymbolAddress((void**)&a1,    s_a1);
    cudaGetSymbolAddress((void**)&h2,    s_h2);
    cudaGetSymbolAddress((void**)&deg,   s_deg);
    cudaGetSymbolAddress((void**)&cnt,   s_cnt);
    cudaGetSymbolAddress((void**)&ex,    s_ex);
    cudaGetSymbolAddress((void**)&row,   s_row);
    cudaGetSymbolAddress((void**)&cur,   s_cur);
    cudaGetSymbolAddress((void**)&bsum,  s_bsum);
    cudaGetSymbolAddress((void**)&src32, s_src);
    cudaGetSymbolAddress((void**)&dst32, s_dst);
    cudaGetSymbolAddress((void**)&colp,  s_col);
    cudaGetSymbolAddress((void**)&val,   s_val);
    cudaGetSymbolAddress((void**)&flag,  s_flag);

    // 1. zero + dtype detect
    gcn_zero_detect<<<nb, 256>>>((const unsigned*)ei, deg, cnt, flag, n);
    // 2. convert + degree/count
    gcn_prep<<<2048, 256>>>(ei, ew, flag, deg, cnt, src32, dst32, n, E);
    // 3-5. rowptr scan (+dinv fused into 3)
    scan_blocks<<<nb, 256>>>(cnt, ex, bsum, deg, n);
    scan_bsums <<<1, NB_MAX>>>(bsum, nb);
    scan_add   <<<nb, 256>>>(ex, bsum, row, cur, n, E);
    // 6. GEMM1 (independent of CSR build; placed here so ncu samples it)
    gcn_gemm<D_IN, D_HID, 64, 32, 4, 6><<<(n + 63) / 64, 128>>>(x, W1, h1, n);
    // 7. CSR build
    gcn_build<<<(E + 255) / 256, 256>>>(src32, dst32, ew, deg, cur, colp, val, E);
    // 8. aggregate layer 1 (fused relu) -> a1
    gcn_agg<D_HID, true><<<(n + 7) / 8, 256>>>(row, colp, val, h1, deg, b1, a1, n);
    // 9. GEMM2
    gcn_gemm<D_HID, D_OUT, 64, 48, 4, 4><<<(n + 63) / 64, 128>>>(a1, W2, h2, n);
    // 10. aggregate layer 2 -> out
    gcn_agg<D_OUT, false><<<(n + 7) / 8, 256>>>(row, colp, val, h2, deg, b2, out, n);
}

// round 7
// speedup vs baseline: 1.1212x; 1.1212x over previous
#include <cuda_runtime.h>
#include <cstdint>

#define D_IN  128
#define D_HID 48
#define D_OUT 32
#define MAX_N 100000
#define MAX_E 1600000
#define NB_MAX 512

// Scratch (module-static device memory — sanctioned no-alloc pattern)
__device__ float s_h1 [MAX_N * D_HID];
__device__ float s_a1 [MAX_N * D_HID];
__device__ float s_h2 [MAX_N * D_OUT];
__device__ float s_deg[MAX_N];
__device__ int   s_cnt[MAX_N];
__device__ int   s_ex [MAX_N];
__device__ int   s_row[MAX_N + 1];
__device__ int   s_cur[MAX_N];
__device__ int   s_bsum[NB_MAX];
__device__ int   s_src[MAX_E];
__device__ int   s_dst[MAX_E];
__device__ int   s_col[MAX_E];
__device__ float s_val[MAX_E];
__device__ int   s_flag[1];

// ---------------------------------------------------------------------------
// zero counters + detect edge_index dtype
// ---------------------------------------------------------------------------
__global__ void gcn_zero_detect(const unsigned* __restrict__ ei_words,
                                float* __restrict__ deg, int* __restrict__ cnt,
                                int* __restrict__ flag, int n) {
    int stride = gridDim.x * blockDim.x;
    for (int i = blockIdx.x * blockDim.x + threadIdx.x; i < n; i += stride) {
        deg[i] = 0.f; cnt[i] = 0;
    }
    if (blockIdx.x == 0 && threadIdx.x == 0) {
        int nz = 0;
        #pragma unroll 8
        for (int i = 1; i < 512; i += 2) nz += (ei_words[i] != 0u);
        flag[0] = (nz == 0) ? 1 : 0;   // int64 => odd words all zero
    }
}

// ---------------------------------------------------------------------------
// convert indices (clamped) + weighted degree + in-degree count
// ---------------------------------------------------------------------------
__global__ void gcn_prep(const void* __restrict__ ei_raw,
                         const float* __restrict__ ew,
                         const int* __restrict__ flag,
                         float* __restrict__ deg, int* __restrict__ cnt,
                         int* __restrict__ src32, int* __restrict__ dst32,
                         int n, int E) {
    int stride = gridDim.x * blockDim.x;
    bool is64 = (flag[0] != 0);
    const long long* ei64 = (const long long*)ei_raw;
    const int*       ei32 = (const int*)ei_raw;
    for (int e = blockIdx.x * blockDim.x + threadIdx.x; e < E; e += stride) {
        int sv, dv;
        if (is64) { sv = (int)ei64[e]; dv = (int)ei64[E + e]; }
        else      { sv = ei32[e];      dv = ei32[E + e]; }
        sv = min(max(sv, 0), n - 1);
        dv = min(max(dv, 0), n - 1);
        src32[e] = sv;
        dst32[e] = dv;
        atomicAdd(deg + dv, ew[e]);
        atomicAdd(cnt + dv, 1);
    }
}

// ---------------------------------------------------------------------------
// per-block scan of cnt (+ fused dinv = rsqrt(deg+1))
// ---------------------------------------------------------------------------
__global__ void scan_blocks(const int* __restrict__ cnt,
                            int* __restrict__ ex, int* __restrict__ bsum,
                            float* __restrict__ deg, int n) {
    __shared__ int sh[256];
    int i = blockIdx.x * 256 + threadIdx.x;
    if (i < n) deg[i] = rsqrtf(deg[i] + 1.0f);   // self-loop weight 1
    int v = (i < n) ? cnt[i] : 0;
    sh[threadIdx.x] = v;
    __syncthreads();
    #pragma unroll
    for (int off = 1; off < 256; off <<= 1) {
        int t = (threadIdx.x >= off) ? sh[threadIdx.x - off] : 0;
        __syncthreads();
        sh[threadIdx.x] += t;
        __syncthreads();
    }
    if (i < n) ex[i] = sh[threadIdx.x] - v;
    if (threadIdx.x == 255) bsum[blockIdx.x] = sh[255];
}

__global__ void scan_bsums(int* __restrict__ bsum, int nb) {
    __shared__ int sh[NB_MAX];
    int v = (threadIdx.x < nb) ? bsum[threadIdx.x] : 0;
    sh[threadIdx.x] = v;
    __syncthreads();
    #pragma unroll
    for (int off = 1; off < NB_MAX; off <<= 1) {
        int t = (threadIdx.x >= off) ? sh[threadIdx.x - off] : 0;
        __syncthreads();
        sh[threadIdx.x] += t;
        __syncthreads();
    }
    if (threadIdx.x < nb) bsum[threadIdx.x] = sh[threadIdx.x] - v;
}

__global__ void scan_add(const int* __restrict__ ex, const int* __restrict__ bsum,
                         int* __restrict__ rowptr, int* __restrict__ cursor,
                         int n, int E) {
    int i = blockIdx.x * 256 + threadIdx.x;
    if (i < n) {
        int r = ex[i] + bsum[blockIdx.x];
        rowptr[i] = r;
        cursor[i] = r;
    }
    if (i == 0) rowptr[n] = E;
}

// ---------------------------------------------------------------------------
// K-tiled fp32 GEMM (float4 global loads)
// ---------------------------------------------------------------------------
template<int DIN, int DOUT, int BM, int BK, int TM, int TN>
__global__ void gcn_gemm(const float* __restrict__ X,
                         const float* __restrict__ W,
                         float* __restrict__ H, int n) {
    constexpr int RT = BM / TM;
    constexpr int CT = DOUT / TN;
    constexpr int NT = RT * CT;

    __shared__ float sXT[BK * (BM + 1)];
    __shared__ float sW [BK * DOUT];

    int tid  = threadIdx.x;
    int row0 = blockIdx.x * BM;
    int ti = tid / CT;
    int tj = tid % CT;

    float acc[TM][TN];
    #pragma unroll
    for (int i = 0; i < TM; i++)
        #pragma unroll
        for (int j = 0; j < TN; j++) acc[i][j] = 0.f;

    for (int k0 = 0; k0 < DIN; k0 += BK) {
        for (int i = tid; i < BM * (BK / 4); i += NT) {
            int r  = i / (BK / 4);
            int c4 = i % (BK / 4);
            float4 v = make_float4(0.f, 0.f, 0.f, 0.f);
            if (row0 + r < n)
                v = *(const float4*)(X + (size_t)(row0 + r) * DIN + k0 + 4 * c4);
            sXT[(4 * c4 + 0) * (BM + 1) + r] = v.x;
            sXT[(4 * c4 + 1) * (BM + 1) + r] = v.y;
            sXT[(4 * c4 + 2) * (BM + 1) + r] = v.z;
            sXT[(4 * c4 + 3) * (BM + 1) + r] = v.w;
        }
        for (int i = tid; i < BK * (DOUT / 4); i += NT) {
            int kk = i / (DOUT / 4);
            int c4 = i % (DOUT / 4);
            float4 v = *(const float4*)(W + (size_t)(k0 + kk) * DOUT + 4 * c4);
            *(float4*)(sW + kk * DOUT + 4 * c4) = v;
        }
        __syncthreads();

        #pragma unroll 4
        for (int kk = 0; kk < BK; kk++) {
            float xr[TM];
            #pragma unroll
            for (int i = 0; i < TM; i++) xr[i] = sXT[kk * (BM + 1) + ti * TM + i];
            #pragma unroll
            for (int j = 0; j < TN; j++) {
                float wv = sW[kk * DOUT + tj * TN + j];
                #pragma unroll
                for (int i = 0; i < TM; i++) acc[i][j] += xr[i] * wv;
            }
        }
        __syncthreads();
    }

    #pragma unroll
    for (int i = 0; i < TM; i++) {
        int r = row0 + ti * TM + i;
        if (r < n) {
            #pragma unroll
            for (int j = 0; j < TN; j++)
                H[(size_t)r * DOUT + tj * TN + j] = acc[i][j];
        }
    }
}

// ---------------------------------------------------------------------------
// CSR build
// ---------------------------------------------------------------------------
__global__ void gcn_build(const int* __restrict__ src32,
                          const int* __restrict__ dst32,
                          const float* __restrict__ ew,
                          const float* __restrict__ dinv,
                          int* __restrict__ cursor,
                          int* __restrict__ col, float* __restrict__ val, int E) {
    int e = blockIdx.x * blockDim.x + threadIdx.x;
    if (e >= E) return;
    int d = dst32[e];
    int pos = atomicAdd(cursor + d, 1);
    int s = src32[e];
    col[pos] = s;
    val[pos] = dinv[s] * ew[e];
}

// ---------------------------------------------------------------------------
// CSR aggregation: warp per node, float2 lanes, 4-edge unroll (MLP=4).
// Fused self-loop + bias (+ relu).
// ---------------------------------------------------------------------------
template<int D, bool RELU>
__global__ void gcn_agg(const int* __restrict__ rowptr,
                        const int* __restrict__ col,
                        const float* __restrict__ val,
                        const float* __restrict__ h,
                        const float* __restrict__ dinv,
                        const float* __restrict__ b,
                        float* __restrict__ out, int n) {
    constexpr int L = D / 2;
    int warp = (blockIdx.x * blockDim.x + threadIdx.x) >> 5;
    int lane = threadIdx.x & 31;
    if (warp >= n) return;

    int r0 = rowptr[warp];
    int r1 = rowptr[warp + 1];
    bool act = lane < L;

    const float2* h2 = (const float2*)h;
    float2 a0 = {0.f, 0.f}, a1 = {0.f, 0.f}, a2 = {0.f, 0.f}, a3 = {0.f, 0.f};

    int idx = r0;
    for (; idx + 3 < r1; idx += 4) {
        int   c0 = col[idx],     c1 = col[idx + 1];
        int   c2 = col[idx + 2], c3 = col[idx + 3];
        float w0 = val[idx],     w1 = val[idx + 1];
        float w2 = val[idx + 2], w3 = val[idx + 3];
        if (act) {
            float2 v0 = h2[(size_t)c0 * L + lane];
            float2 v1 = h2[(size_t)c1 * L + lane];
            float2 v2 = h2[(size_t)c2 * L + lane];
            float2 v3 = h2[(size_t)c3 * L + lane];
            a0.x += w0 * v0.x; a0.y += w0 * v0.y;
            a1.x += w1 * v1.x; a1.y += w1 * v1.y;
            a2.x += w2 * v2.x; a2.y += w2 * v2.y;
            a3.x += w3 * v3.x; a3.y += w3 * v3.y;
        }
    }
    for (; idx < r1; idx++) {
        int   c = col[idx];
        float w = val[idx];
        if (act) {
            float2 v = h2[(size_t)c * L + lane];
            a0.x += w * v.x; a0.y += w * v.y;
        }
    }

    if (act) {
        float2 A;
        A.x = (a0.x + a1.x) + (a2.x + a3.x);
        A.y = (a0.y + a1.y) + (a2.y + a3.y);

        float di = dinv[warp];
        float2 hv = h2[(size_t)warp * L + lane];
        float2 bb = ((const float2*)b)[lane];
        float2 o;
        o.x = di * A.x + di * di * hv.x + bb.x;
        o.y = di * A.y + di * di * hv.y + bb.y;
        if (RELU) { o.x = fmaxf(o.x, 0.f); o.y = fmaxf(o.y, 0.f); }
        ((float2*)out)[(size_t)warp * L + lane] = o;
    }
}

// ---------------------------------------------------------------------------
extern "C" void kernel_launch(void* const* d_in, const int* in_sizes, int n_in,
                              void* d_out, int out_size) {
    const float* x  = (const float*)d_in[0];
    const void*  ei = d_in[1];
    const float* ew = (const float*)d_in[2];
    const float* W1 = (const float*)d_in[3];
    const float* b1 = (const float*)d_in[4];
    const float* W2 = (const float*)d_in[5];
    const float* b2 = (const float*)d_in[6];
    float*       out = (float*)d_out;

    int n = in_sizes[0] / D_IN;      // 100000
    int E = in_sizes[2];             // 1600000
    int nb = (n + 255) / 256;

    float *h1, *a1, *h2, *deg, *val;
    int *cnt, *ex, *row, *cur, *bsum, *src32, *dst32, *colp, *flag;
    cudaGetSymbolAddress((void**)&h1,    s_h1);
    cudaGetSymbolAddress((void**)&a1,    s_a1);
    cudaGetSymbolAddress((void**)&h2,    s_h2);
    cudaGetSymbolAddress((void**)&deg,   s_deg);
    cudaGetSymbolAddress((void**)&cnt,   s_cnt);
    cudaGetSymbolAddress((void**)&ex,    s_ex);
    cudaGetSymbolAddress((void**)&row,   s_row);
    cudaGetSymbolAddress((void**)&cur,   s_cur);
    cudaGetSymbolAddress((void**)&bsum,  s_bsum);
    cudaGetSymbolAddress((void**)&src32, s_src);
    cudaGetSymbolAddress((void**)&dst32, s_dst);
    cudaGetSymbolAddress((void**)&colp,  s_col);
    cudaGetSymbolAddress((void**)&val,   s_val);
    cudaGetSymbolAddress((void**)&flag,  s_flag);

    // One-time host resources (created on the uncaptured correctness call;
    // no device memory involved). Work per call is identical.
    static cudaStream_t st2 = nullptr;
    static cudaEvent_t  evFork = nullptr, evJoin = nullptr;
    if (st2 == nullptr) {
        cudaStreamCreateWithFlags(&st2, cudaStreamNonBlocking);
        cudaEventCreateWithFlags(&evFork, cudaEventDisableTiming);
        cudaEventCreateWithFlags(&evJoin, cudaEventDisableTiming);
    }

    // ---- fork: GEMM1 depends only on x, W1 — run it beside the CSR chain ----
    cudaEventRecord(evFork, 0);
    cudaStreamWaitEvent(st2, evFork, 0);
    gcn_gemm<D_IN, D_HID, 64, 32, 4, 6><<<(n + 63) / 64, 128, 0, st2>>>(x, W1, h1, n);
    cudaEventRecord(evJoin, st2);

    // ---- main chain: CSR construction ----
    gcn_zero_detect<<<nb, 256>>>((const unsigned*)ei, deg, cnt, flag, n);
    gcn_prep<<<2048, 256>>>(ei, ew, flag, deg, cnt, src32, dst32, n, E);
    scan_blocks<<<nb, 256>>>(cnt, ex, bsum, deg, n);
    scan_bsums <<<1, NB_MAX>>>(bsum, nb);
    scan_add   <<<nb, 256>>>(ex, bsum, row, cur, n, E);
    gcn_build<<<(E + 255) / 256, 256>>>(src32, dst32, ew, deg, cur, colp, val, E);

    // ---- join: aggregation needs both h1 and the CSR ----
    cudaStreamWaitEvent(0, evJoin, 0);
    gcn_agg<D_HID, true><<<(n + 7) / 8, 256>>>(row, colp, val, h1, deg, b1, a1, n);
    gcn_gemm<D_HID, D_OUT, 64, 48, 4, 4><<<(n + 63) / 64, 128>>>(a1, W2, h2, n);
    gcn_agg<D_OUT, false><<<(n + 7) / 8, 256>>>(row, colp, val, h2, deg, b2, out, n);
}

// round 8
// speedup vs baseline: 1.1563x; 1.0313x over previous
#include <cuda_runtime.h>
#include <cstdint>

#define D_IN  128
#define D_HID 48
#define D_OUT 32
#define MAX_N 100000
#define MAX_E 1600000
#define NB_MAX 512

// Scratch (module-static device memory — sanctioned no-alloc pattern)
__device__ float s_h1 [MAX_N * D_HID];
__device__ float s_h2 [MAX_N * D_OUT];
__device__ float s_deg[MAX_N];
__device__ int   s_cnt[MAX_N];
__device__ int   s_ex [MAX_N];
__device__ int   s_row[MAX_N + 1];
__device__ int   s_cur[MAX_N];
__device__ int   s_bsum[NB_MAX];
__device__ int   s_col[MAX_E];
__device__ float s_val[MAX_E];
__device__ int   s_flag[1];

// ---------------------------------------------------------------------------
// zero counters + detect edge_index dtype (int64 => odd 32-bit words all zero)
// ---------------------------------------------------------------------------
__global__ void gcn_zero_detect(const unsigned* __restrict__ ei_words,
                                float* __restrict__ deg, int* __restrict__ cnt,
                                int* __restrict__ flag, int n) {
    int stride = gridDim.x * blockDim.x;
    for (int i = blockIdx.x * blockDim.x + threadIdx.x; i < n; i += stride) {
        deg[i] = 0.f; cnt[i] = 0;
    }
    if (blockIdx.x == 0 && threadIdx.x == 0) {
        int nz = 0;
        #pragma unroll 8
        for (int i = 1; i < 512; i += 2) nz += (ei_words[i] != 0u);
        flag[0] = (nz == 0) ? 1 : 0;
    }
}

// ---------------------------------------------------------------------------
// index decode helper
// ---------------------------------------------------------------------------
__device__ __forceinline__ void decode_edge(const void* ei_raw, bool is64,
                                            int e, int E, int n,
                                            int& s, int& d) {
    if (is64) {
        const long long* p = (const long long*)ei_raw;
        s = (int)p[e]; d = (int)p[E + e];
    } else {
        const int* p = (const int*)ei_raw;
        s = p[e]; d = p[E + e];
    }
    s = min(max(s, 0), n - 1);
    d = min(max(d, 0), n - 1);
}

// ---------------------------------------------------------------------------
// weighted degree + in-degree count (atomics only; indices not materialized)
// ---------------------------------------------------------------------------
__global__ void gcn_prep(const void* __restrict__ ei_raw,
                         const float* __restrict__ ew,
                         const int* __restrict__ flag,
                         float* __restrict__ deg, int* __restrict__ cnt,
                         int n, int E) {
    int stride = gridDim.x * blockDim.x;
    bool is64 = (flag[0] != 0);
    for (int e = blockIdx.x * blockDim.x + threadIdx.x; e < E; e += stride) {
        int s, d;
        decode_edge(ei_raw, is64, e, E, n, s, d);
        atomicAdd(deg + d, ew[e]);
        atomicAdd(cnt + d, 1);
    }
}

// ---------------------------------------------------------------------------
// per-block scan of cnt (+ fused dinv = rsqrt(deg+1))
// ---------------------------------------------------------------------------
__global__ void scan_blocks(const int* __restrict__ cnt,
                            int* __restrict__ ex, int* __restrict__ bsum,
                            float* __restrict__ deg, int n) {
    __shared__ int sh[256];
    int i = blockIdx.x * 256 + threadIdx.x;
    if (i < n) deg[i] = rsqrtf(deg[i] + 1.0f);   // self-loop weight 1
    int v = (i < n) ? cnt[i] : 0;
    sh[threadIdx.x] = v;
    __syncthreads();
    #pragma unroll
    for (int off = 1; off < 256; off <<= 1) {
        int t = (threadIdx.x >= off) ? sh[threadIdx.x - off] : 0;
        __syncthreads();
        sh[threadIdx.x] += t;
        __syncthreads();
    }
    if (i < n) ex[i] = sh[threadIdx.x] - v;
    if (threadIdx.x == 255) bsum[blockIdx.x] = sh[255];
}

// each block redundantly scans bsum in smem, then finalizes its 256 nodes
__global__ void scan_finish(const int* __restrict__ ex,
                            const int* __restrict__ bsum,
                            int* __restrict__ rowptr, int* __restrict__ cursor,
                            int n, int E, int nb) {
    __shared__ int sh[NB_MAX];
    __shared__ int shex[NB_MAX];
    int t = threadIdx.x;                     // 512 threads
    int v = (t < nb) ? bsum[t] : 0;
    sh[t] = v;
    __syncthreads();
    #pragma unroll
    for (int off = 1; off < NB_MAX; off <<= 1) {
        int tmp = (t >= off) ? sh[t - off] : 0;
        __syncthreads();
        sh[t] += tmp;
        __syncthreads();
    }
    shex[t] = sh[t] - v;                     // exclusive
    __syncthreads();
    int base = shex[blockIdx.x];
    if (t < 256) {
        int i = blockIdx.x * 256 + t;
        if (i < n) {
            int r = ex[i] + base;
            rowptr[i] = r;
            cursor[i] = r;
        }
        if (i == 0) rowptr[n] = E;
    }
}

// ---------------------------------------------------------------------------
// CSR build (re-decodes edge_index directly)
// ---------------------------------------------------------------------------
__global__ void gcn_build(const void* __restrict__ ei_raw,
                          const float* __restrict__ ew,
                          const int* __restrict__ flag,
                          const float* __restrict__ dinv,
                          int* __restrict__ cursor,
                          int* __restrict__ col, float* __restrict__ val,
                          int n, int E) {
    int e = blockIdx.x * blockDim.x + threadIdx.x;
    if (e >= E) return;
    bool is64 = (flag[0] != 0);
    int s, d;
    decode_edge(ei_raw, is64, e, E, n, s, d);
    int pos = atomicAdd(cursor + d, 1);
    col[pos] = s;
    val[pos] = dinv[s] * ew[e];
}

// ---------------------------------------------------------------------------
// K-tiled fp32 GEMM (float4 global loads) — used for GEMM1 only
// ---------------------------------------------------------------------------
template<int DIN, int DOUT, int BM, int BK, int TM, int TN>
__global__ void gcn_gemm(const float* __restrict__ X,
                         const float* __restrict__ W,
                         float* __restrict__ H, int n) {
    constexpr int RT = BM / TM;
    constexpr int CT = DOUT / TN;
    constexpr int NT = RT * CT;

    __shared__ float sXT[BK * (BM + 1)];
    __shared__ float sW [BK * DOUT];

    int tid  = threadIdx.x;
    int row0 = blockIdx.x * BM;
    int ti = tid / CT;
    int tj = tid % CT;

    float acc[TM][TN];
    #pragma unroll
    for (int i = 0; i < TM; i++)
        #pragma unroll
        for (int j = 0; j < TN; j++) acc[i][j] = 0.f;

    for (int k0 = 0; k0 < DIN; k0 += BK) {
        for (int i = tid; i < BM * (BK / 4); i += NT) {
            int r  = i / (BK / 4);
            int c4 = i % (BK / 4);
            float4 v = make_float4(0.f, 0.f, 0.f, 0.f);
            if (row0 + r < n)
                v = *(const float4*)(X + (size_t)(row0 + r) * DIN + k0 + 4 * c4);
            sXT[(4 * c4 + 0) * (BM + 1) + r] = v.x;
            sXT[(4 * c4 + 1) * (BM + 1) + r] = v.y;
            sXT[(4 * c4 + 2) * (BM + 1) + r] = v.z;
            sXT[(4 * c4 + 3) * (BM + 1) + r] = v.w;
        }
        for (int i = tid; i < BK * (DOUT / 4); i += NT) {
            int kk = i / (DOUT / 4);
            int c4 = i % (DOUT / 4);
            float4 v = *(const float4*)(W + (size_t)(k0 + kk) * DOUT + 4 * c4);
            *(float4*)(sW + kk * DOUT + 4 * c4) = v;
        }
        __syncthreads();

        #pragma unroll 4
        for (int kk = 0; kk < BK; kk++) {
            float xr[TM];
            #pragma unroll
            for (int i = 0; i < TM; i++) xr[i] = sXT[kk * (BM + 1) + ti * TM + i];
            #pragma unroll
            for (int j = 0; j < TN; j++) {
                float wv = sW[kk * DOUT + tj * TN + j];
                #pragma unroll
                for (int i = 0; i < TM; i++) acc[i][j] += xr[i] * wv;
            }
        }
        __syncthreads();
    }

    #pragma unroll
    for (int i = 0; i < TM; i++) {
        int r = row0 + ti * TM + i;
        if (r < n) {
            #pragma unroll
            for (int j = 0; j < TN; j++)
                H[(size_t)r * DOUT + tj * TN + j] = acc[i][j];
        }
    }
}

// ---------------------------------------------------------------------------
// Fused layer-1 aggregate + relu + GEMM2:
//   a1row = relu(dinv*Σ val*h1[col] + dinv²*h1[v] + b1)   (in registers/smem)
//   h2[v] = a1row @ W2                                     (lane per out-col)
// Warp per node; 256 threads = 8 warps per block.
// ---------------------------------------------------------------------------
__global__ void gcn_agg1_gemm2(const int* __restrict__ rowptr,
                               const int* __restrict__ col,
                               const float* __restrict__ val,
                               const float* __restrict__ h,   // h1
                               const float* __restrict__ dinv,
                               const float* __restrict__ b,   // b1
                               const float* __restrict__ W2,
                               float* __restrict__ h2out, int n) {
    constexpr int L = D_HID / 2;             // 24 active float2 lanes
    __shared__ float sW2[D_HID * D_OUT];     // 48*32 = 6 KB
    __shared__ float stage[8][D_HID];        // per-warp a1 row

    // load W2 once
    for (int i = threadIdx.x; i < D_HID * D_OUT / 4; i += blockDim.x)
        *(float4*)(sW2 + 4 * i) = *(const float4*)(W2 + 4 * i);
    __syncthreads();

    int wI   = threadIdx.x >> 5;             // warp in block
    int warp = (blockIdx.x * blockDim.x + threadIdx.x) >> 5;
    int lane = threadIdx.x & 31;
    if (warp >= n) return;

    int r0 = rowptr[warp];
    int r1 = rowptr[warp + 1];
    bool act = lane < L;

    const float2* hh = (const float2*)h;
    float2 a0 = {0.f, 0.f}, a1 = {0.f, 0.f}, a2 = {0.f, 0.f}, a3 = {0.f, 0.f};

    int idx = r0;
    for (; idx + 3 < r1; idx += 4) {
        int   c0 = col[idx],     c1 = col[idx + 1];
        int   c2 = col[idx + 2], c3 = col[idx + 3];
        float w0 = val[idx],     w1 = val[idx + 1];
        float w2 = val[idx + 2], w3 = val[idx + 3];
        if (act) {
            float2 v0 = hh[(size_t)c0 * L + lane];
            float2 v1 = hh[(size_t)c1 * L + lane];
            float2 v2 = hh[(size_t)c2 * L + lane];
            float2 v3 = hh[(size_t)c3 * L + lane];
            a0.x += w0 * v0.x; a0.y += w0 * v0.y;
            a1.x += w1 * v1.x; a1.y += w1 * v1.y;
            a2.x += w2 * v2.x; a2.y += w2 * v2.y;
            a3.x += w3 * v3.x; a3.y += w3 * v3.y;
        }
    }
    for (; idx < r1; idx++) {
        int   c = col[idx];
        float w = val[idx];
        if (act) {
            float2 v = hh[(size_t)c * L + lane];
            a0.x += w * v.x; a0.y += w * v.y;
        }
    }

    if (act) {
        float2 A;
        A.x = (a0.x + a1.x) + (a2.x + a3.x);
        A.y = (a0.y + a1.y) + (a2.y + a3.y);
        float di = dinv[warp];
        float2 hv = hh[(size_t)warp * L + lane];
        float2 bb = ((const float2*)b)[lane];
        float2 o;
        o.x = fmaxf(di * A.x + di * di * hv.x + bb.x, 0.f);
        o.y = fmaxf(di * A.y + di * di * hv.y + bb.y, 0.f);
        *(float2*)(&stage[wI][2 * lane]) = o;
    }
    __syncwarp();

    // GEMM2 row: each lane computes one of the 32 output columns
    float acc = 0.f;
    #pragma unroll 8
    for (int k = 0; k < D_HID; k++)
        acc += stage[wI][k] * sW2[k * D_OUT + lane];
    h2out[(size_t)warp * D_OUT + lane] = acc;
}

// ---------------------------------------------------------------------------
// Layer-2 aggregate, full 32 lanes: half-warps own alternate edges (2 edges in
// flight), unrolled x2 (4 edges in flight), shfl_xor(16) combine.
//   out = dinv*Σ val*h2[col] + dinv²*h2[v] + b2
// ---------------------------------------------------------------------------
__global__ void gcn_agg2(const int* __restrict__ rowptr,
                         const int* __restrict__ col,
                         const float* __restrict__ val,
                         const float* __restrict__ h,      // h2
                         const float* __restrict__ dinv,
                         const float* __restrict__ b,      // b2
                         float* __restrict__ out, int n) {
    constexpr int L = D_OUT / 2;             // 16 float2 lanes per edge
    int warp = (blockIdx.x * blockDim.x + threadIdx.x) >> 5;
    int lane = threadIdx.x & 31;
    if (warp >= n) return;

    int r0 = rowptr[warp];
    int r1 = rowptr[warp + 1];
    int hi   = lane >> 4;                    // 0: even edges, 1: odd edges
    int flan = lane & 15;                    // feature pair index

    const float2* hh = (const float2*)h;
    float2 a0 = {0.f, 0.f}, a1 = {0.f, 0.f};

    for (int idx = r0 + hi; idx < r1; idx += 4) {
        int   c = col[idx];
        float w = val[idx];
        float2 v = hh[(size_t)c * L + flan];
        a0.x += w * v.x; a0.y += w * v.y;
        int idx2 = idx + 2;
        if (idx2 < r1) {
            int   c2 = col[idx2];
            float w2 = val[idx2];
            float2 v2 = hh[(size_t)c2 * L + flan];
            a1.x += w2 * v2.x; a1.y += w2 * v2.y;
        }
    }
    float Ax = (a0.x + a1.x), Ay = (a0.y + a1.y);
    Ax += __shfl_xor_sync(0xffffffffu, Ax, 16);
    Ay += __shfl_xor_sync(0xffffffffu, Ay, 16);

    if (hi == 0) {
        float di = dinv[warp];
        float2 hv = hh[(size_t)warp * L + flan];
        float2 bb = ((const float2*)b)[flan];
        float2 o;
        o.x = di * Ax + di * di * hv.x + bb.x;
        o.y = di * Ay + di * di * hv.y + bb.y;
        ((float2*)out)[(size_t)warp * L + flan] = o;
    }
}

// ---------------------------------------------------------------------------
extern "C" void kernel_launch(void* const* d_in, const int* in_sizes, int n_in,
                              void* d_out, int out_size) {
    const float* x  = (const float*)d_in[0];
    const void*  ei = d_in[1];
    const float* ew = (const float*)d_in[2];
    const float* W1 = (const float*)d_in[3];
    const float* b1 = (const float*)d_in[4];
    const float* W2 = (const float*)d_in[5];
    const float* b2 = (const float*)d_in[6];
    float*       out = (float*)d_out;

    int n = in_sizes[0] / D_IN;      // 100000
    int E = in_sizes[2];             // 1600000
    int nb = (n + 255) / 256;        // 391

    float *h1, *h2, *deg, *val;
    int *cnt, *ex, *row, *cur, *bsum, *colp, *flag;
    cudaGetSymbolAddress((void**)&h1,   s_h1);
    cudaGetSymbolAddress((void**)&h2,   s_h2);
    cudaGetSymbolAddress((void**)&deg,  s_deg);
    cudaGetSymbolAddress((void**)&cnt,  s_cnt);
    cudaGetSymbolAddress((void**)&ex,   s_ex);
    cudaGetSymbolAddress((void**)&row,  s_row);
    cudaGetSymbolAddress((void**)&cur,  s_cur);
    cudaGetSymbolAddress((void**)&bsum, s_bsum);
    cudaGetSymbolAddress((void**)&colp, s_col);
    cudaGetSymbolAddress((void**)&val,  s_val);
    cudaGetSymbolAddress((void**)&flag, s_flag);

    // One-time host resources (no device memory)
    static cudaStream_t st2 = nullptr;
    static cudaEvent_t  evFork = nullptr, evJoin = nullptr;
    if (st2 == nullptr) {
        cudaStreamCreateWithFlags(&st2, cudaStreamNonBlocking);
        cudaEventCreateWithFlags(&evFork, cudaEventDisableTiming);
        cudaEventCreateWithFlags(&evJoin, cudaEventDisableTiming);
    }

    // ---- fork: GEMM1 beside the CSR chain ----
    cudaEventRecord(evFork, 0);
    cudaStreamWaitEvent(st2, evFork, 0);
    gcn_gemm<D_IN, D_HID, 64, 32, 4, 6><<<(n + 63) / 64, 128, 0, st2>>>(x, W1, h1, n);
    cudaEventRecord(evJoin, st2);

    // ---- main chain: CSR construction ----
    gcn_zero_detect<<<nb, 256>>>((const unsigned*)ei, deg, cnt, flag, n);
    gcn_prep<<<2048, 256>>>(ei, ew, flag, deg, cnt, n, E);
    scan_blocks<<<nb, 256>>>(cnt, ex, bsum, deg, n);
    scan_finish<<<nb, NB_MAX>>>(ex, bsum, row, cur, n, E, nb);
    gcn_build<<<(E + 255) / 256, 256>>>(ei, ew, flag, deg, cur, colp, val, n, E);

    // ---- join: fused agg1+gemm2, then agg2 ----
    cudaStreamWaitEvent(0, evJoin, 0);
    gcn_agg1_gemm2<<<(n + 7) / 8, 256>>>(row, colp, val, h1, deg, b1, W2, h2, n);
    gcn_agg2<<<(n + 7) / 8, 256>>>(row, colp, val, h2, deg, b2, out, n);
}

// round 9
// speedup vs baseline: 1.2466x; 1.0782x over previous
#include <cuda_runtime.h>
#include <cuda_fp16.h>
#include <cstdint>

#define D_IN  128
#define D_HID 48
#define D_OUT 32
#define MAX_N 100000
#define MAX_E 1600000
#define NB_MAX 512

#define FIX_SCALE 16777216.0f          // 2^24
#define FIX_INV   (1.0f / 16777216.0f)

// Scratch (module-static device memory — sanctioned no-alloc pattern)
__device__ __half2             s_h1h[MAX_N * (D_HID / 2)];  // h1 fp16
__device__ __half2             s_h2h[MAX_N * (D_OUT / 2)];  // h2 fp16
__device__ unsigned long long  s_pack[MAX_N];               // count<<32 | fix(deg)
__device__ float               s_deg [MAX_N];               // dinv
__device__ int                 s_ex  [MAX_N];               // block-local scan
__device__ int                 s_row [MAX_N + 1];           // CSR rowptr
__device__ int                 s_bsum[NB_MAX];
__device__ unsigned short      s_seq [MAX_E];               // within-node sequence
__device__ float2              s_edge[MAX_E];               // {col bits, val}
__device__ int                 s_flag[1];

// ---------------------------------------------------------------------------
// zero pack + detect edge_index dtype (int64 => odd 32-bit words all zero)
// ---------------------------------------------------------------------------
__global__ void gcn_zero_detect(const unsigned* __restrict__ ei_words,
                                unsigned long long* __restrict__ pack,
                                int* __restrict__ flag, int n) {
    int stride = gridDim.x * blockDim.x;
    for (int i = blockIdx.x * blockDim.x + threadIdx.x; i < n; i += stride)
        pack[i] = 0ull;
    if (blockIdx.x == 0 && threadIdx.x == 0) {
        int nz = 0;
        #pragma unroll 8
        for (int i = 1; i < 512; i += 2) nz += (ei_words[i] != 0u);
        flag[0] = (nz == 0) ? 1 : 0;
    }
}

__device__ __forceinline__ void decode_edge(const void* ei_raw, bool is64,
                                            int e, int E, int n,
                                            int& s, int& d) {
    if (is64) {
        const long long* p = (const long long*)ei_raw;
        s = (int)p[e]; d = (int)p[E + e];
    } else {
        const int* p = (const int*)ei_raw;
        s = p[e]; d = p[E + e];
    }
    s = min(max(s, 0), n - 1);
    d = min(max(d, 0), n - 1);
}

// ---------------------------------------------------------------------------
// prep: single packed 64-bit atomic per edge; returns sequence number
// ---------------------------------------------------------------------------
__global__ void gcn_prep(const void* __restrict__ ei_raw,
                         const float* __restrict__ ew,
                         const int* __restrict__ flag,
                         unsigned long long* __restrict__ pack,
                         unsigned short* __restrict__ seq,
                         int n, int E) {
    int stride = gridDim.x * blockDim.x;
    bool is64 = (flag[0] != 0);
    for (int e = blockIdx.x * blockDim.x + threadIdx.x; e < E; e += stride) {
        int s, d;
        decode_edge(ei_raw, is64, e, E, n, s, d);
        unsigned q = (unsigned)__float2uint_rn(ew[e] * FIX_SCALE);
        unsigned long long old =
            atomicAdd(pack + d, 0x100000000ull + (unsigned long long)q);
        seq[e] = (unsigned short)(old >> 32);
    }
}

// ---------------------------------------------------------------------------
// per-block scan of counts (+ fused dinv from fixed-point degree)
// ---------------------------------------------------------------------------
__global__ void scan_blocks(const unsigned long long* __restrict__ pack,
                            int* __restrict__ ex, int* __restrict__ bsum,
                            float* __restrict__ deg, int n) {
    __shared__ int sh[256];
    int i = blockIdx.x * 256 + threadIdx.x;
    int v = 0;
    if (i < n) {
        unsigned long long p = pack[i];
        v = (int)(p >> 32);
        float dsum = (float)(unsigned)(p & 0xffffffffull) * FIX_INV;
        deg[i] = rsqrtf(dsum + 1.0f);          // self-loop weight 1
    }
    sh[threadIdx.x] = v;
    __syncthreads();
    #pragma unroll
    for (int off = 1; off < 256; off <<= 1) {
        int t = (threadIdx.x >= off) ? sh[threadIdx.x - off] : 0;
        __syncthreads();
        sh[threadIdx.x] += t;
        __syncthreads();
    }
    if (i < n) ex[i] = sh[threadIdx.x] - v;
    if (threadIdx.x == 255) bsum[blockIdx.x] = sh[255];
}

// each block redundantly scans bsum in smem, then finalizes its 256 nodes
__global__ void scan_finish(const int* __restrict__ ex,
                            const int* __restrict__ bsum,
                            int* __restrict__ rowptr,
                            int n, int E, int nb) {
    __shared__ int sh[NB_MAX];
    __shared__ int shex[NB_MAX];
    int t = threadIdx.x;                       // 512 threads
    int v = (t < nb) ? bsum[t] : 0;
    sh[t] = v;
    __syncthreads();
    #pragma unroll
    for (int off = 1; off < NB_MAX; off <<= 1) {
        int tmp = (t >= off) ? sh[t - off] : 0;
        __syncthreads();
        sh[t] += tmp;
        __syncthreads();
    }
    shex[t] = sh[t] - v;
    __syncthreads();
    int base = shex[blockIdx.x];
    if (t < 256) {
        int i = blockIdx.x * 256 + t;
        if (i < n) rowptr[i] = ex[i] + base;
        if (i == 0) rowptr[n] = E;
    }
}

// ---------------------------------------------------------------------------
// CSR build: atomic-free (pos = rowptr[dst] + seq), 8B packed edge record
// ---------------------------------------------------------------------------
__global__ void gcn_build(const void* __restrict__ ei_raw,
                          const float* __restrict__ ew,
                          const int* __restrict__ flag,
                          const float* __restrict__ dinv,
                          const int* __restrict__ rowptr,
                          const unsigned short* __restrict__ seq,
                          float2* __restrict__ edge,
                          int n, int E) {
    int e = blockIdx.x * blockDim.x + threadIdx.x;
    if (e >= E) return;
    bool is64 = (flag[0] != 0);
    int s, d;
    decode_edge(ei_raw, is64, e, E, n, s, d);
    int pos = rowptr[d] + (int)seq[e];
    float2 rec;
    rec.x = __int_as_float(s);
    rec.y = dinv[s] * ew[e];
    edge[pos] = rec;
}

// ---------------------------------------------------------------------------
// GEMM1: h1 = x @ W1, output converted to fp16 (half2)
// ---------------------------------------------------------------------------
template<int DIN, int DOUT, int BM, int BK, int TM, int TN>
__global__ void gcn_gemm1(const float* __restrict__ X,
                          const float* __restrict__ W,
                          __half2* __restrict__ H, int n) {
    constexpr int RT = BM / TM;
    constexpr int CT = DOUT / TN;
    constexpr int NT = RT * CT;
    static_assert(TN % 2 == 0, "TN even for half2 packing");

    __shared__ float sXT[BK * (BM + 1)];
    __shared__ float sW [BK * DOUT];

    int tid  = threadIdx.x;
    int row0 = blockIdx.x * BM;
    int ti = tid / CT;
    int tj = tid % CT;

    float acc[TM][TN];
    #pragma unroll
    for (int i = 0; i < TM; i++)
        #pragma unroll
        for (int j = 0; j < TN; j++) acc[i][j] = 0.f;

    for (int k0 = 0; k0 < DIN; k0 += BK) {
        for (int i = tid; i < BM * (BK / 4); i += NT) {
            int r  = i / (BK / 4);
            int c4 = i % (BK / 4);
            float4 v = make_float4(0.f, 0.f, 0.f, 0.f);
            if (row0 + r < n)
                v = *(const float4*)(X + (size_t)(row0 + r) * DIN + k0 + 4 * c4);
            sXT[(4 * c4 + 0) * (BM + 1) + r] = v.x;
            sXT[(4 * c4 + 1) * (BM + 1) + r] = v.y;
            sXT[(4 * c4 + 2) * (BM + 1) + r] = v.z;
            sXT[(4 * c4 + 3) * (BM + 1) + r] = v.w;
        }
        for (int i = tid; i < BK * (DOUT / 4); i += NT) {
            int kk = i / (DOUT / 4);
            int c4 = i % (DOUT / 4);
            float4 v = *(const float4*)(W + (size_t)(k0 + kk) * DOUT + 4 * c4);
            *(float4*)(sW + kk * DOUT + 4 * c4) = v;
        }
        __syncthreads();

        #pragma unroll 4
        for (int kk = 0; kk < BK; kk++) {
            float xr[TM];
            #pragma unroll
            for (int i = 0; i < TM; i++) xr[i] = sXT[kk * (BM + 1) + ti * TM + i];
            #pragma unroll
            for (int j = 0; j < TN; j++) {
                float wv = sW[kk * DOUT + tj * TN + j];
                #pragma unroll
                for (int i = 0; i < TM; i++) acc[i][j] += xr[i] * wv;
            }
        }
        __syncthreads();
    }

    #pragma unroll
    for (int i = 0; i < TM; i++) {
        int r = row0 + ti * TM + i;
        if (r < n) {
            #pragma unroll
            for (int j = 0; j < TN; j += 2) {
                __half2 hv = __floats2half2_rn(acc[i][j], acc[i][j + 1]);
                H[(size_t)r * (DOUT / 2) + (tj * TN + j) / 2] = hv;
            }
        }
    }
}

// ---------------------------------------------------------------------------
// Fused layer-1 aggregate + relu + GEMM2 (fp16 gathers, 8B edge records)
// ---------------------------------------------------------------------------
__global__ void gcn_agg1_gemm2(const int* __restrict__ rowptr,
                               const float2* __restrict__ edge,
                               const __half2* __restrict__ h,   // h1 fp16
                               const float* __restrict__ dinv,
                               const float* __restrict__ b,     // b1
                               const float* __restrict__ W2,
                               __half2* __restrict__ h2out, int n) {
    constexpr int L = D_HID / 2;             // 24 active lanes
    __shared__ float sW2[D_HID * D_OUT];     // 6 KB
    __shared__ float stage[8][D_HID];

    for (int i = threadIdx.x; i < D_HID * D_OUT / 4; i += blockDim.x)
        *(float4*)(sW2 + 4 * i) = *(const float4*)(W2 + 4 * i);
    __syncthreads();

    int wI   = threadIdx.x >> 5;
    int warp = (blockIdx.x * blockDim.x + threadIdx.x) >> 5;
    int lane = threadIdx.x & 31;
    if (warp >= n) return;

    int r0 = rowptr[warp];
    int r1 = rowptr[warp + 1];
    bool act = lane < L;

    float2 a0 = {0.f, 0.f}, a1 = {0.f, 0.f}, a2 = {0.f, 0.f}, a3 = {0.f, 0.f};

    int idx = r0;
    for (; idx + 3 < r1; idx += 4) {
        float2 e0 = edge[idx],     e1 = edge[idx + 1];
        float2 e2 = edge[idx + 2], e3 = edge[idx + 3];
        if (act) {
            float2 v0 = __half22float2(h[(size_t)__float_as_int(e0.x) * L + lane]);
            float2 v1 = __half22float2(h[(size_t)__float_as_int(e1.x) * L + lane]);
            float2 v2 = __half22float2(h[(size_t)__float_as_int(e2.x) * L + lane]);
            float2 v3 = __half22float2(h[(size_t)__float_as_int(e3.x) * L + lane]);
            a0.x += e0.y * v0.x; a0.y += e0.y * v0.y;
            a1.x += e1.y * v1.x; a1.y += e1.y * v1.y;
            a2.x += e2.y * v2.x; a2.y += e2.y * v2.y;
            a3.x += e3.y * v3.x; a3.y += e3.y * v3.y;
        }
    }
    for (; idx < r1; idx++) {
        float2 er = edge[idx];
        if (act) {
            float2 v = __half22float2(h[(size_t)__float_as_int(er.x) * L + lane]);
            a0.x += er.y * v.x; a0.y += er.y * v.y;
        }
    }

    if (act) {
        float2 A;
        A.x = (a0.x + a1.x) + (a2.x + a3.x);
        A.y = (a0.y + a1.y) + (a2.y + a3.y);
        float di = dinv[warp];
        float2 hv = __half22float2(h[(size_t)warp * L + lane]);
        float2 bb = ((const float2*)b)[lane];
        float2 o;
        o.x = fmaxf(di * A.x + di * di * hv.x + bb.x, 0.f);
        o.y = fmaxf(di * A.y + di * di * hv.y + bb.y, 0.f);
        *(float2*)(&stage[wI][2 * lane]) = o;
    }
    __syncwarp();

    // GEMM2 row: lane -> one of 32 output columns; pack pairs via shfl
    float acc = 0.f;
    #pragma unroll 8
    for (int k = 0; k < D_HID; k++)
        acc += stage[wI][k] * sW2[k * D_OUT + lane];
    float accR = __shfl_down_sync(0xffffffffu, acc, 1);
    if ((lane & 1) == 0)
        h2out[(size_t)warp * (D_OUT / 2) + (lane >> 1)] = __floats2half2_rn(acc, accR);
}

// ---------------------------------------------------------------------------
// Layer-2 aggregate: half-warps own alternate edges, fp16 gathers
// ---------------------------------------------------------------------------
__global__ void gcn_agg2(const int* __restrict__ rowptr,
                         const float2* __restrict__ edge,
                         const __half2* __restrict__ h,   // h2 fp16
                         const float* __restrict__ dinv,
                         const float* __restrict__ b,     // b2
                         float* __restrict__ out, int n) {
    constexpr int L = D_OUT / 2;             // 16 half2 lanes per edge
    int warp = (blockIdx.x * blockDim.x + threadIdx.x) >> 5;
    int lane = threadIdx.x & 31;
    if (warp >= n) return;

    int r0 = rowptr[warp];
    int r1 = rowptr[warp + 1];
    int hi   = lane >> 4;
    int flan = lane & 15;

    float2 a0 = {0.f, 0.f}, a1 = {0.f, 0.f};

    for (int idx = r0 + hi; idx < r1; idx += 4) {
        float2 er = edge[idx];
        float2 v = __half22float2(h[(size_t)__float_as_int(er.x) * L + flan]);
        a0.x += er.y * v.x; a0.y += er.y * v.y;
        int idx2 = idx + 2;
        if (idx2 < r1) {
            float2 er2 = edge[idx2];
            float2 v2 = __half22float2(h[(size_t)__float_as_int(er2.x) * L + flan]);
            a1.x += er2.y * v2.x; a1.y += er2.y * v2.y;
        }
    }
    float Ax = (a0.x + a1.x), Ay = (a0.y + a1.y);
    Ax += __shfl_xor_sync(0xffffffffu, Ax, 16);
    Ay += __shfl_xor_sync(0xffffffffu, Ay, 16);

    if (hi == 0) {
        float di = dinv[warp];
        float2 hv = __half22float2(h[(size_t)warp * L + flan]);
        float2 bb = ((const float2*)b)[flan];
        float2 o;
        o.x = di * Ax + di * di * hv.x + bb.x;
        o.y = di * Ay + di * di * hv.y + bb.y;
        ((float2*)out)[(size_t)warp * L + flan] = o;
    }
}

// ---------------------------------------------------------------------------
extern "C" void kernel_launch(void* const* d_in, const int* in_sizes, int n_in,
                              void* d_out, int out_size) {
    const float* x  = (const float*)d_in[0];
    const void*  ei = d_in[1];
    const float* ew = (const float*)d_in[2];
    const float* W1 = (const float*)d_in[3];
    const float* b1 = (const float*)d_in[4];
    const float* W2 = (const float*)d_in[5];
    const float* b2 = (const float*)d_in[6];
    float*       out = (float*)d_out;

    int n = in_sizes[0] / D_IN;      // 100000
    int E = in_sizes[2];             // 1600000
    int nb = (n + 255) / 256;        // 391

    __half2 *h1h, *h2h;
    unsigned long long* pack;
    float *deg;
    int *ex, *row, *bsum, *flag;
    unsigned short* seq;
    float2* edge;
    cudaGetSymbolAddress((void**)&h1h,  s_h1h);
    cudaGetSymbolAddress((void**)&h2h,  s_h2h);
    cudaGetSymbolAddress((void**)&pack, s_pack);
    cudaGetSymbolAddress((void**)&deg,  s_deg);
    cudaGetSymbolAddress((void**)&ex,   s_ex);
    cudaGetSymbolAddress((void**)&row,  s_row);
    cudaGetSymbolAddress((void**)&bsum, s_bsum);
    cudaGetSymbolAddress((void**)&seq,  s_seq);
    cudaGetSymbolAddress((void**)&edge, s_edge);
    cudaGetSymbolAddress((void**)&flag, s_flag);

    // One-time host resources (no device memory)
    static cudaStream_t st2 = nullptr;
    static cudaEvent_t  evFork = nullptr, evJoin = nullptr;
    if (st2 == nullptr) {
        cudaStreamCreateWithFlags(&st2, cudaStreamNonBlocking);
        cudaEventCreateWithFlags(&evFork, cudaEventDisableTiming);
        cudaEventCreateWithFlags(&evJoin, cudaEventDisableTiming);
    }

    // ---- fork: GEMM1 beside the CSR chain ----
    cudaEventRecord(evFork, 0);
    cudaStreamWaitEvent(st2, evFork, 0);
    gcn_gemm1<D_IN, D_HID, 64, 32, 4, 6><<<(n + 63) / 64, 128, 0, st2>>>(x, W1, h1h, n);
    cudaEventRecord(evJoin, st2);

    // ---- main chain: CSR construction ----
    gcn_zero_detect<<<nb, 256>>>((const unsigned*)ei, pack, flag, n);
    gcn_prep<<<2048, 256>>>(ei, ew, flag, pack, seq, n, E);
    scan_blocks<<<nb, 256>>>(pack, ex, bsum, deg, n);
    scan_finish<<<nb, NB_MAX>>>(ex, bsum, row, n, E, nb);
    gcn_build<<<(E + 255) / 256, 256>>>(ei, ew, flag, deg, row, seq, edge, n, E);

    // ---- join: fused agg1+gemm2, then agg2 ----
    cudaStreamWaitEvent(0, evJoin, 0);
    gcn_agg1_gemm2<<<(n + 7) / 8, 256>>>(row, edge, h1h, deg, b1, W2, h2h, n);
    gcn_agg2<<<(n + 7) / 8, 256>>>(row, edge, h2h, deg, b2, out, n);
}

// round 10
// speedup vs baseline: 1.2818x; 1.0282x over previous
#include <cuda_runtime.h>
#include <cuda_fp16.h>
#include <cstdint>

#define D_IN  128
#define D_HID 48
#define D_OUT 32
#define MAX_N 100000
#define MAX_E 1600000
#define NB_MAX 512

#define FIX_SCALE 16777216.0f          // 2^24
#define FIX_INV   (1.0f / 16777216.0f)

// Scratch (module-static device memory — sanctioned no-alloc pattern)
// s_pack layout: [0, MAX_N)      = per-node pack: count<<32 | fix(deg)
//                [MAX_N, +NB_MAX) = scan lookback state (status<<62 | value)
__device__ unsigned long long  s_pack[MAX_N + NB_MAX];
__device__ __half2             s_h1h[MAX_N * (D_HID / 2)];  // h1 fp16
__device__ __half2             s_h2h[MAX_N * (D_OUT / 2)];  // h2 fp16
__device__ float               s_deg [MAX_N];               // dinv
__device__ int                 s_row [MAX_N + 1];           // CSR rowptr
__device__ unsigned short      s_seq [MAX_E];               // within-node sequence
__device__ float2              s_edge[MAX_E];               // {col bits, val}
__device__ int                 s_flag[1];

// ---------------------------------------------------------------------------
// dtype detect (runs on side stream): int64 => odd 32-bit words all zero
// ---------------------------------------------------------------------------
__global__ void gcn_detect(const unsigned* __restrict__ ei_words,
                           int* __restrict__ flag) {
    if (threadIdx.x == 0 && blockIdx.x == 0) {
        int nz = 0;
        #pragma unroll 8
        for (int i = 1; i < 512; i += 2) nz += (ei_words[i] != 0u);
        flag[0] = (nz == 0) ? 1 : 0;
    }
}

__device__ __forceinline__ void decode_edge(const void* ei_raw, bool is64,
                                            int e, int E, int n,
                                            int& s, int& d) {
    if (is64) {
        const long long* p = (const long long*)ei_raw;
        s = (int)p[e]; d = (int)p[E + e];
    } else {
        const int* p = (const int*)ei_raw;
        s = p[e]; d = p[E + e];
    }
    s = min(max(s, 0), n - 1);
    d = min(max(d, 0), n - 1);
}

// ---------------------------------------------------------------------------
// prep: decode dst only; single packed 64-bit atomic per edge; record seq
// ---------------------------------------------------------------------------
__global__ void gcn_prep(const void* __restrict__ ei_raw,
                         const float* __restrict__ ew,
                         const int* __restrict__ flag,
                         unsigned long long* __restrict__ pack,
                         unsigned short* __restrict__ seq,
                         int n, int E) {
    int stride = gridDim.x * blockDim.x;
    bool is64 = (flag[0] != 0);
    for (int e = blockIdx.x * blockDim.x + threadIdx.x; e < E; e += stride) {
        int d;
        if (is64) d = (int)((const long long*)ei_raw)[E + e];
        else      d = ((const int*)ei_raw)[E + e];
        d = min(max(d, 0), n - 1);
        unsigned q = (unsigned)__float2uint_rn(ew[e] * FIX_SCALE);
        unsigned long long old =
            atomicAdd(pack + d, 0x100000000ull + (unsigned long long)q);
        seq[e] = (unsigned short)(old >> 32);
    }
}

// ---------------------------------------------------------------------------
// single-pass exclusive scan (decoupled lookback, warp-parallel) + fused dinv
// state[blk]: bits 62-63 = status (0 none, 1 aggregate, 2 prefix), low 32 = value
// ---------------------------------------------------------------------------
__global__ void scan_lookback(const unsigned long long* __restrict__ pack,
                              unsigned long long* state,
                              int* __restrict__ rowptr,
                              float* __restrict__ deg, int n, int E) {
    __shared__ int sh[256];
    __shared__ int s_base;
    int blk = blockIdx.x;
    int tid = threadIdx.x;
    int i = blk * 256 + tid;

    int v = 0;
    if (i < n) {
        unsigned long long p = pack[i];
        v = (int)(p >> 32);
        float dsum = (float)(unsigned)(p & 0xffffffffull) * FIX_INV;
        deg[i] = rsqrtf(dsum + 1.0f);          // self-loop weight 1
    }
    sh[tid] = v;
    __syncthreads();
    #pragma unroll
    for (int off = 1; off < 256; off <<= 1) {
        int t = (tid >= off) ? sh[tid - off] : 0;
        __syncthreads();
        sh[tid] += t;
        __syncthreads();
    }
    int total = sh[255];

    if (tid == 0) {
        __threadfence();
        atomicExch(state + blk, (1ull << 62) | (unsigned long long)(unsigned)total);
    }

    if (tid < 32) {
        int run = 0;
        if (blk > 0) {
            int j = blk - 1;
            while (true) {
                int idx = j - (int)tid;        // lane 0 = nearest predecessor
                unsigned long long s = (2ull << 62);   // idx<0 => prefix 0
                if (idx >= 0) {
                    do { s = ((volatile unsigned long long*)state)[idx]; }
                    while ((s >> 62) == 0ull);
                }
                unsigned pm = __ballot_sync(0xffffffffu,
                                            (idx < 0) || ((s >> 62) == 2ull));
                int firstPref = __ffs(pm) - 1; // closest lane holding a prefix
                int contrib = (int)(unsigned)(s & 0xffffffffull);
                if (idx < 0) contrib = 0;
                if (pm && (int)tid > firstPref) contrib = 0;
                #pragma unroll
                for (int o = 16; o > 0; o >>= 1)
                    contrib += __shfl_down_sync(0xffffffffu, contrib, o);
                run += __shfl_sync(0xffffffffu, contrib, 0);
                if (pm) break;
                j -= 32;
            }
        }
        if (tid == 0) {
            __threadfence();
            atomicExch(state + blk,
                       (2ull << 62) | (unsigned long long)(unsigned)(run + total));
            s_base = run;
        }
    }
    __syncthreads();

    int base = s_base;
    if (i < n) rowptr[i] = base + sh[tid] - v;   // exclusive prefix
    if (i == 0) rowptr[n] = E;
}

// ---------------------------------------------------------------------------
// CSR build: atomic-free (pos = rowptr[dst] + seq), 8B packed edge record
// ---------------------------------------------------------------------------
__global__ void gcn_build(const void* __restrict__ ei_raw,
                          const float* __restrict__ ew,
                          const int* __restrict__ flag,
                          const float* __restrict__ dinv,
                          const int* __restrict__ rowptr,
                          const unsigned short* __restrict__ seq,
                          float2* __restrict__ edge,
                          int n, int E) {
    int e = blockIdx.x * blockDim.x + threadIdx.x;
    if (e >= E) return;
    bool is64 = (flag[0] != 0);
    int s, d;
    decode_edge(ei_raw, is64, e, E, n, s, d);
    int pos = rowptr[d] + (int)seq[e];
    float2 rec;
    rec.x = __int_as_float(s);
    rec.y = dinv[s] * ew[e];
    edge[pos] = rec;
}

// ---------------------------------------------------------------------------
// GEMM1: h1 = x @ W1, output converted to fp16 (half2)
// ---------------------------------------------------------------------------
template<int DIN, int DOUT, int BM, int BK, int TM, int TN>
__global__ void gcn_gemm1(const float* __restrict__ X,
                          const float* __restrict__ W,
                          __half2* __restrict__ H, int n) {
    constexpr int RT = BM / TM;
    constexpr int CT = DOUT / TN;
    constexpr int NT = RT * CT;
    static_assert(TN % 2 == 0, "TN even for half2 packing");

    __shared__ float sXT[BK * (BM + 1)];
    __shared__ float sW [BK * DOUT];

    int tid  = threadIdx.x;
    int row0 = blockIdx.x * BM;
    int ti = tid / CT;
    int tj = tid % CT;

    float acc[TM][TN];
    #pragma unroll
    for (int i = 0; i < TM; i++)
        #pragma unroll
        for (int j = 0; j < TN; j++) acc[i][j] = 0.f;

    for (int k0 = 0; k0 < DIN; k0 += BK) {
        for (int i = tid; i < BM * (BK / 4); i += NT) {
            int r  = i / (BK / 4);
            int c4 = i % (BK / 4);
            float4 v = make_float4(0.f, 0.f, 0.f, 0.f);
            if (row0 + r < n)
                v = *(const float4*)(X + (size_t)(row0 + r) * DIN + k0 + 4 * c4);
            sXT[(4 * c4 + 0) * (BM + 1) + r] = v.x;
            sXT[(4 * c4 + 1) * (BM + 1) + r] = v.y;
            sXT[(4 * c4 + 2) * (BM + 1) + r] = v.z;
            sXT[(4 * c4 + 3) * (BM + 1) + r] = v.w;
        }
        for (int i = tid; i < BK * (DOUT / 4); i += NT) {
            int kk = i / (DOUT / 4);
            int c4 = i % (DOUT / 4);
            float4 v = *(const float4*)(W + (size_t)(k0 + kk) * DOUT + 4 * c4);
            *(float4*)(sW + kk * DOUT + 4 * c4) = v;
        }
        __syncthreads();

        #pragma unroll 4
        for (int kk = 0; kk < BK; kk++) {
            float xr[TM];
            #pragma unroll
            for (int i = 0; i < TM; i++) xr[i] = sXT[kk * (BM + 1) + ti * TM + i];
            #pragma unroll
            for (int j = 0; j < TN; j++) {
                float wv = sW[kk * DOUT + tj * TN + j];
                #pragma unroll
                for (int i = 0; i < TM; i++) acc[i][j] += xr[i] * wv;
            }
        }
        __syncthreads();
    }

    #pragma unroll
    for (int i = 0; i < TM; i++) {
        int r = row0 + ti * TM + i;
        if (r < n) {
            #pragma unroll
            for (int j = 0; j < TN; j += 2) {
                __half2 hv = __floats2half2_rn(acc[i][j], acc[i][j + 1]);
                H[(size_t)r * (DOUT / 2) + (tj * TN + j) / 2] = hv;
            }
        }
    }
}

// ---------------------------------------------------------------------------
// Fused layer-1 aggregate + relu + GEMM2 (fp16 gathers, 8B edge records)
// ---------------------------------------------------------------------------
__global__ void gcn_agg1_gemm2(const int* __restrict__ rowptr,
                               const float2* __restrict__ edge,
                               const __half2* __restrict__ h,   // h1 fp16
                               const float* __restrict__ dinv,
                               const float* __restrict__ b,     // b1
                               const float* __restrict__ W2,
                               __half2* __restrict__ h2out, int n) {
    constexpr int L = D_HID / 2;             // 24 active lanes
    __shared__ float sW2[D_HID * D_OUT];     // 6 KB
    __shared__ float stage[8][D_HID];

    for (int i = threadIdx.x; i < D_HID * D_OUT / 4; i += blockDim.x)
        *(float4*)(sW2 + 4 * i) = *(const float4*)(W2 + 4 * i);
    __syncthreads();

    int wI   = threadIdx.x >> 5;
    int warp = (blockIdx.x * blockDim.x + threadIdx.x) >> 5;
    int lane = threadIdx.x & 31;
    if (warp >= n) return;

    int r0 = rowptr[warp];
    int r1 = rowptr[warp + 1];
    bool act = lane < L;

    float2 a0 = {0.f, 0.f}, a1 = {0.f, 0.f}, a2 = {0.f, 0.f}, a3 = {0.f, 0.f};

    int idx = r0;
    for (; idx + 3 < r1; idx += 4) {
        float2 e0 = edge[idx],     e1 = edge[idx + 1];
        float2 e2 = edge[idx + 2], e3 = edge[idx + 3];
        if (act) {
            float2 v0 = __half22float2(h[(size_t)__float_as_int(e0.x) * L + lane]);
            float2 v1 = __half22float2(h[(size_t)__float_as_int(e1.x) * L + lane]);
            float2 v2 = __half22float2(h[(size_t)__float_as_int(e2.x) * L + lane]);
            float2 v3 = __half22float2(h[(size_t)__float_as_int(e3.x) * L + lane]);
            a0.x += e0.y * v0.x; a0.y += e0.y * v0.y;
            a1.x += e1.y * v1.x; a1.y += e1.y * v1.y;
            a2.x += e2.y * v2.x; a2.y += e2.y * v2.y;
            a3.x += e3.y * v3.x; a3.y += e3.y * v3.y;
        }
    }
    for (; idx < r1; idx++) {
        float2 er = edge[idx];
        if (act) {
            float2 v = __half22float2(h[(size_t)__float_as_int(er.x) * L + lane]);
            a0.x += er.y * v.x; a0.y += er.y * v.y;
        }
    }

    if (act) {
        float2 A;
        A.x = (a0.x + a1.x) + (a2.x + a3.x);
        A.y = (a0.y + a1.y) + (a2.y + a3.y);
        float di = dinv[warp];
        float2 hv = __half22float2(h[(size_t)warp * L + lane]);
        float2 bb = ((const float2*)b)[lane];
        float2 o;
        o.x = fmaxf(di * A.x + di * di * hv.x + bb.x, 0.f);
        o.y = fmaxf(di * A.y + di * di * hv.y + bb.y, 0.f);
        *(float2*)(&stage[wI][2 * lane]) = o;
    }
    __syncwarp();

    // GEMM2 row: lane -> one of 32 output columns; pack pairs via shfl
    float acc = 0.f;
    #pragma unroll 8
    for (int k = 0; k < D_HID; k++)
        acc += stage[wI][k] * sW2[k * D_OUT + lane];
    float accR = __shfl_down_sync(0xffffffffu, acc, 1);
    if ((lane & 1) == 0)
        h2out[(size_t)warp * (D_OUT / 2) + (lane >> 1)] = __floats2half2_rn(acc, accR);
}

// ---------------------------------------------------------------------------
// Layer-2 aggregate: half-warps own alternate edges, fp16 gathers
// ---------------------------------------------------------------------------
__global__ void gcn_agg2(const int* __restrict__ rowptr,
                         const float2* __restrict__ edge,
                         const __half2* __restrict__ h,   // h2 fp16
                         const float* __restrict__ dinv,
                         const float* __restrict__ b,     // b2
                         float* __restrict__ out, int n) {
    constexpr int L = D_OUT / 2;             // 16 half2 lanes per edge
    int warp = (blockIdx.x * blockDim.x + threadIdx.x) >> 5;
    int lane = threadIdx.x & 31;
    if (warp >= n) return;

    int r0 = rowptr[warp];
    int r1 = rowptr[warp + 1];
    int hi   = lane >> 4;
    int flan = lane & 15;

    float2 a0 = {0.f, 0.f}, a1 = {0.f, 0.f};

    for (int idx = r0 + hi; idx < r1; idx += 4) {
        float2 er = edge[idx];
        float2 v = __half22float2(h[(size_t)__float_as_int(er.x) * L + flan]);
        a0.x += er.y * v.x; a0.y += er.y * v.y;
        int idx2 = idx + 2;
        if (idx2 < r1) {
            float2 er2 = edge[idx2];
            float2 v2 = __half22float2(h[(size_t)__float_as_int(er2.x) * L + flan]);
            a1.x += er2.y * v2.x; a1.y += er2.y * v2.y;
        }
    }
    float Ax = (a0.x + a1.x), Ay = (a0.y + a1.y);
    Ax += __shfl_xor_sync(0xffffffffu, Ax, 16);
    Ay += __shfl_xor_sync(0xffffffffu, Ay, 16);

    if (hi == 0) {
        float di = dinv[warp];
        float2 hv = __half22float2(h[(size_t)warp * L + flan]);
        float2 bb = ((const float2*)b)[flan];
        float2 o;
        o.x = di * Ax + di * di * hv.x + bb.x;
        o.y = di * Ay + di * di * hv.y + bb.y;
        ((float2*)out)[(size_t)warp * L + flan] = o;
    }
}

// ---------------------------------------------------------------------------
extern "C" void kernel_launch(void* const* d_in, const int* in_sizes, int n_in,
                              void* d_out, int out_size) {
    const float* x  = (const float*)d_in[0];
    const void*  ei = d_in[1];
    const float* ew = (const float*)d_in[2];
    const float* W1 = (const float*)d_in[3];
    const float* b1 = (const float*)d_in[4];
    const float* W2 = (const float*)d_in[5];
    const float* b2 = (const float*)d_in[6];
    float*       out = (float*)d_out;

    int n = in_sizes[0] / D_IN;      // 100000
    int E = in_sizes[2];             // 1600000
    int nb = (n + 255) / 256;        // 391

    __half2 *h1h, *h2h;
    unsigned long long* pack;
    float* deg;
    int *row, *flag;
    unsigned short* seq;
    float2* edge;
    cudaGetSymbolAddress((void**)&pack, s_pack);
    cudaGetSymbolAddress((void**)&h1h,  s_h1h);
    cudaGetSymbolAddress((void**)&h2h,  s_h2h);
    cudaGetSymbolAddress((void**)&deg,  s_deg);
    cudaGetSymbolAddress((void**)&row,  s_row);
    cudaGetSymbolAddress((void**)&seq,  s_seq);
    cudaGetSymbolAddress((void**)&edge, s_edge);
    cudaGetSymbolAddress((void**)&flag, s_flag);
    unsigned long long* scstate = pack + MAX_N;   // lookback state region

    // One-time host resources (no device memory)
    static cudaStream_t st2 = nullptr;
    static cudaEvent_t  evFork = nullptr, evDet = nullptr, evJoin = nullptr;
    if (st2 == nullptr) {
        cudaStreamCreateWithFlags(&st2, cudaStreamNonBlocking);
        cudaEventCreateWithFlags(&evFork, cudaEventDisableTiming);
        cudaEventCreateWithFlags(&evDet,  cudaEventDisableTiming);
        cudaEventCreateWithFlags(&evJoin, cudaEventDisableTiming);
    }

    // ---- fork: detect + GEMM1 on side stream ----
    cudaEventRecord(evFork, 0);
    cudaStreamWaitEvent(st2, evFork, 0);
    gcn_detect<<<1, 32, 0, st2>>>((const unsigned*)ei, flag);
    cudaEventRecord(evDet, st2);
    gcn_gemm1<D_IN, D_HID, 64, 32, 4, 6><<<(n + 63) / 64, 128, 0, st2>>>(x, W1, h1h, n);
    cudaEventRecord(evJoin, st2);

    // ---- main chain ----
    cudaMemsetAsync(pack, 0, (size_t)(MAX_N + NB_MAX) * sizeof(unsigned long long), 0);
    cudaStreamWaitEvent(0, evDet, 0);
    gcn_prep<<<2048, 256>>>(ei, ew, flag, pack, seq, n, E);
    scan_lookback<<<nb, 256>>>(pack, scstate, row, deg, n, E);
    gcn_build<<<(E + 255) / 256, 256>>>(ei, ew, flag, deg, row, seq, edge, n, E);

    // ---- join: fused agg1+gemm2, then agg2 ----
    cudaStreamWaitEvent(0, evJoin, 0);
    gcn_agg1_gemm2<<<(n + 7) / 8, 256>>>(row, edge, h1h, deg, b1, W2, h2h, n);
    gcn_agg2<<<(n + 7) / 8, 256>>>(row, edge, h2h, deg, b2, out, n);
}

// round 11
// speedup vs baseline: 1.2997x; 1.0139x over previous
#include <cuda_runtime.h>
#include <cuda_fp16.h>
#include <cstdint>

#define D_IN  128
#define D_HID 48
#define D_OUT 32
#define MAX_N 100000
#define MAX_E 1600000
#define NB_MAX 512

#define FIX_SCALE 16777216.0f          // 2^24
#define FIX_INV   (1.0f / 16777216.0f)

// Scratch (module-static device memory — sanctioned no-alloc pattern)
// s_pack: [0, MAX_N) per-node pack (count<<32 | fix(deg)); [MAX_N,+NB_MAX) scan state
__device__ unsigned long long  s_pack[MAX_N + NB_MAX];
__device__ __half2             s_h1h[MAX_N * (D_HID / 2)];  // h1 fp16
__device__ __half2             s_h2h[MAX_N * (D_OUT / 2)];  // h2 fp16
__device__ float               s_deg [MAX_N];               // dinv
__device__ int                 s_row [MAX_N + 1];           // CSR rowptr
__device__ unsigned            s_pos [MAX_E];               // (dst<<12)|seq
__device__ float2              s_edge[MAX_E];               // {col bits, val}
__device__ int                 s_flag[1];

// ---------------------------------------------------------------------------
// side stream: zero pack+state and detect edge_index dtype
// ---------------------------------------------------------------------------
__global__ void gcn_zdet(const unsigned* __restrict__ ei_words,
                         unsigned long long* __restrict__ pack,
                         int* __restrict__ flag) {
    int stride = gridDim.x * blockDim.x;
    for (int i = blockIdx.x * blockDim.x + threadIdx.x; i < MAX_N + NB_MAX; i += stride)
        pack[i] = 0ull;
    if (blockIdx.x == 0 && threadIdx.x == 0) {
        int nz = 0;
        #pragma unroll 8
        for (int i = 1; i < 512; i += 2) nz += (ei_words[i] != 0u);
        flag[0] = (nz == 0) ? 1 : 0;   // int64 => odd 32-bit words all zero
    }
}

// ---------------------------------------------------------------------------
// prep: decode dst only; one packed 64-bit atomic per edge; emit (dst<<12)|seq
// ---------------------------------------------------------------------------
__global__ void gcn_prep(const void* __restrict__ ei_raw,
                         const float* __restrict__ ew,
                         const int* __restrict__ flag,
                         unsigned long long* __restrict__ pack,
                         unsigned* __restrict__ pos32,
                         int n, int E) {
    int stride = gridDim.x * blockDim.x;
    bool is64 = (flag[0] != 0);
    for (int e = blockIdx.x * blockDim.x + threadIdx.x; e < E; e += stride) {
        int d;
        if (is64) d = (int)((const long long*)ei_raw)[E + e];
        else      d = ((const int*)ei_raw)[E + e];
        d = min(max(d, 0), n - 1);
        unsigned q = (unsigned)__float2uint_rn(ew[e] * FIX_SCALE);
        unsigned long long old =
            atomicAdd(pack + d, 0x100000000ull + (unsigned long long)q);
        unsigned seq = min((unsigned)(old >> 32), 4095u);
        pos32[e] = ((unsigned)d << 12) | seq;
    }
}

// ---------------------------------------------------------------------------
// single-pass exclusive scan (decoupled lookback) + fused dinv
// ---------------------------------------------------------------------------
__global__ void scan_lookback(const unsigned long long* __restrict__ pack,
                              unsigned long long* state,
                              int* __restrict__ rowptr,
                              float* __restrict__ deg, int n, int E) {
    __shared__ int sh[256];
    __shared__ int s_base;
    int blk = blockIdx.x;
    int tid = threadIdx.x;
    int i = blk * 256 + tid;

    int v = 0;
    if (i < n) {
        unsigned long long p = pack[i];
        v = (int)(p >> 32);
        float dsum = (float)(unsigned)(p & 0xffffffffull) * FIX_INV;
        deg[i] = rsqrtf(dsum + 1.0f);          // self-loop weight 1
    }
    sh[tid] = v;
    __syncthreads();
    #pragma unroll
    for (int off = 1; off < 256; off <<= 1) {
        int t = (tid >= off) ? sh[tid - off] : 0;
        __syncthreads();
        sh[tid] += t;
        __syncthreads();
    }
    int total = sh[255];

    if (tid == 0) {
        __threadfence();
        atomicExch(state + blk, (1ull << 62) | (unsigned long long)(unsigned)total);
    }

    if (tid < 32) {
        int run = 0;
        if (blk > 0) {
            int j = blk - 1;
            while (true) {
                int idx = j - (int)tid;
                unsigned long long s = (2ull << 62);
                if (idx >= 0) {
                    do { s = ((volatile unsigned long long*)state)[idx]; }
                    while ((s >> 62) == 0ull);
                }
                unsigned pm = __ballot_sync(0xffffffffu,
                                            (idx < 0) || ((s >> 62) == 2ull));
                int firstPref = __ffs(pm) - 1;
                int contrib = (int)(unsigned)(s & 0xffffffffull);
                if (idx < 0) contrib = 0;
                if (pm && (int)tid > firstPref) contrib = 0;
                #pragma unroll
                for (int o = 16; o > 0; o >>= 1)
                    contrib += __shfl_down_sync(0xffffffffu, contrib, o);
                run += __shfl_sync(0xffffffffu, contrib, 0);
                if (pm) break;
                j -= 32;
            }
        }
        if (tid == 0) {
            __threadfence();
            atomicExch(state + blk,
                       (2ull << 62) | (unsigned long long)(unsigned)(run + total));
            s_base = run;
        }
    }
    __syncthreads();

    int base = s_base;
    if (i < n) rowptr[i] = base + sh[tid] - v;
    if (i == 0) rowptr[n] = E;
}

// ---------------------------------------------------------------------------
// CSR build: decode src only; pos from packed (dst<<12)|seq; 8B edge record
// ---------------------------------------------------------------------------
__global__ void gcn_build(const void* __restrict__ ei_raw,
                          const float* __restrict__ ew,
                          const int* __restrict__ flag,
                          const float* __restrict__ dinv,
                          const int* __restrict__ rowptr,
                          const unsigned* __restrict__ pos32,
                          float2* __restrict__ edge,
                          int n, int E) {
    int e = blockIdx.x * blockDim.x + threadIdx.x;
    if (e >= E) return;
    bool is64 = (flag[0] != 0);
    int s;
    if (is64) s = (int)((const long long*)ei_raw)[e];
    else      s = ((const int*)ei_raw)[e];
    s = min(max(s, 0), n - 1);
    unsigned p = pos32[e];
    int pos = rowptr[p >> 12] + (int)(p & 0xfffu);
    float2 rec;
    rec.x = __int_as_float(s);
    rec.y = dinv[s] * ew[e];
    edge[pos] = rec;
}

// ---------------------------------------------------------------------------
// GEMM1: h1 = x @ W1, output fp16
// ---------------------------------------------------------------------------
template<int DIN, int DOUT, int BM, int BK, int TM, int TN>
__global__ void gcn_gemm1(const float* __restrict__ X,
                          const float* __restrict__ W,
                          __half2* __restrict__ H, int n) {
    constexpr int RT = BM / TM;
    constexpr int CT = DOUT / TN;
    constexpr int NT = RT * CT;
    static_assert(TN % 2 == 0, "TN even");

    __shared__ float sXT[BK * (BM + 1)];
    __shared__ float sW [BK * DOUT];

    int tid  = threadIdx.x;
    int row0 = blockIdx.x * BM;
    int ti = tid / CT;
    int tj = tid % CT;

    float acc[TM][TN];
    #pragma unroll
    for (int i = 0; i < TM; i++)
        #pragma unroll
        for (int j = 0; j < TN; j++) acc[i][j] = 0.f;

    for (int k0 = 0; k0 < DIN; k0 += BK) {
        for (int i = tid; i < BM * (BK / 4); i += NT) {
            int r  = i / (BK / 4);
            int c4 = i % (BK / 4);
            float4 v = make_float4(0.f, 0.f, 0.f, 0.f);
            if (row0 + r < n)
                v = *(const float4*)(X + (size_t)(row0 + r) * DIN + k0 + 4 * c4);
            sXT[(4 * c4 + 0) * (BM + 1) + r] = v.x;
            sXT[(4 * c4 + 1) * (BM + 1) + r] = v.y;
            sXT[(4 * c4 + 2) * (BM + 1) + r] = v.z;
            sXT[(4 * c4 + 3) * (BM + 1) + r] = v.w;
        }
        for (int i = tid; i < BK * (DOUT / 4); i += NT) {
            int kk = i / (DOUT / 4);
            int c4 = i % (DOUT / 4);
            float4 v = *(const float4*)(W + (size_t)(k0 + kk) * DOUT + 4 * c4);
            *(float4*)(sW + kk * DOUT + 4 * c4) = v;
        }
        __syncthreads();

        #pragma unroll 4
        for (int kk = 0; kk < BK; kk++) {
            float xr[TM];
            #pragma unroll
            for (int i = 0; i < TM; i++) xr[i] = sXT[kk * (BM + 1) + ti * TM + i];
            #pragma unroll
            for (int j = 0; j < TN; j++) {
                float wv = sW[kk * DOUT + tj * TN + j];
                #pragma unroll
                for (int i = 0; i < TM; i++) acc[i][j] += xr[i] * wv;
            }
        }
        __syncthreads();
    }

    #pragma unroll
    for (int i = 0; i < TM; i++) {
        int r = row0 + ti * TM + i;
        if (r < n) {
            #pragma unroll
            for (int j = 0; j < TN; j += 2) {
                __half2 hv = __floats2half2_rn(acc[i][j], acc[i][j + 1]);
                H[(size_t)r * (DOUT / 2) + (tj * TN + j) / 2] = hv;
            }
        }
    }
}

// ---------------------------------------------------------------------------
// Fused layer-1 aggregate + relu + GEMM2.
// Warp = 2×16-lane groups; each group owns alternate edges; active sub-lane
// t<12 loads float2 (4 halves) of the 96B h1 row. shfl_xor(16) combine.
// ---------------------------------------------------------------------------
__global__ void gcn_agg1_gemm2(const int* __restrict__ rowptr,
                               const float2* __restrict__ edge,
                               const __half2* __restrict__ h,   // h1 fp16
                               const float* __restrict__ dinv,
                               const float* __restrict__ b,     // b1
                               const float* __restrict__ W2,
                               __half2* __restrict__ h2out, int n) {
    constexpr int LQ = D_HID / 4;            // 12 float2 per row
    __shared__ float sW2[D_HID * D_OUT];     // 6 KB
    __shared__ float stage[16][D_HID];       // 16 warps (512 threads)

    for (int i = threadIdx.x; i < D_HID * D_OUT / 4; i += blockDim.x)
        *(float4*)(sW2 + 4 * i) = *(const float4*)(W2 + 4 * i);
    __syncthreads();

    int wI   = threadIdx.x >> 5;
    int warp = (blockIdx.x * blockDim.x + threadIdx.x) >> 5;
    int lane = threadIdx.x & 31;
    if (warp >= n) return;

    int r0 = rowptr[warp];
    int r1 = rowptr[warp + 1];
    int g    = lane >> 4;                    // group 0/1
    int t    = lane & 15;                    // sub-lane
    bool act = t < LQ;

    const float2* h4 = (const float2*)h;     // 2×half2 per element
    float4 a0 = {0.f,0.f,0.f,0.f}, a1 = {0.f,0.f,0.f,0.f};

    for (int idx = r0 + g; idx < r1; idx += 4) {
        float2 er = edge[idx];
        if (act) {
            float2 raw = h4[(size_t)__float_as_int(er.x) * LQ + t];
            float2 p0 = __half22float2(*(const __half2*)&raw.x);
            float2 p1 = __half22float2(*(const __half2*)&raw.y);
            a0.x += er.y * p0.x; a0.y += er.y * p0.y;
            a0.z += er.y * p1.x; a0.w += er.y * p1.y;
        }
        int idx2 = idx + 2;
        if (idx2 < r1) {
            float2 er2 = edge[idx2];
            if (act) {
                float2 raw = h4[(size_t)__float_as_int(er2.x) * LQ + t];
                float2 p0 = __half22float2(*(const __half2*)&raw.x);
                float2 p1 = __half22float2(*(const __half2*)&raw.y);
                a1.x += er2.y * p0.x; a1.y += er2.y * p0.y;
                a1.z += er2.y * p1.x; a1.w += er2.y * p1.y;
            }
        }
    }
    float4 A;
    A.x = a0.x + a1.x; A.y = a0.y + a1.y;
    A.z = a0.z + a1.z; A.w = a0.w + a1.w;
    A.x += __shfl_xor_sync(0xffffffffu, A.x, 16);
    A.y += __shfl_xor_sync(0xffffffffu, A.y, 16);
    A.z += __shfl_xor_sync(0xffffffffu, A.z, 16);
    A.w += __shfl_xor_sync(0xffffffffu, A.w, 16);

    if (g == 0 && act) {
        float di = dinv[warp];
        float2 raw = h4[(size_t)warp * LQ + t];
        float2 p0 = __half22float2(*(const __half2*)&raw.x);
        float2 p1 = __half22float2(*(const __half2*)&raw.y);
        float4 bb = ((const float4*)b)[t];
        float4 o;
        o.x = fmaxf(di * A.x + di * di * p0.x + bb.x, 0.f);
        o.y = fmaxf(di * A.y + di * di * p0.y + bb.y, 0.f);
        o.z = fmaxf(di * A.z + di * di * p1.x + bb.z, 0.f);
        o.w = fmaxf(di * A.w + di * di * p1.y + bb.w, 0.f);
        *(float4*)(&stage[wI][4 * t]) = o;
    }
    __syncwarp();

    // GEMM2 row: lane -> one of 32 output columns; pack pairs via shfl
    float acc = 0.f;
    #pragma unroll 8
    for (int k = 0; k < D_HID; k++)
        acc += stage[wI][k] * sW2[k * D_OUT + lane];
    float accR = __shfl_down_sync(0xffffffffu, acc, 1);
    if ((lane & 1) == 0)
        h2out[(size_t)warp * (D_OUT / 2) + (lane >> 1)] = __floats2half2_rn(acc, accR);
}

// ---------------------------------------------------------------------------
// Layer-2 aggregate: 4×8-lane groups; each lane loads float2 (4 halves) of
// the 64B h2 row; shfl_xor(8,16) combine; float4 epilogue store.
// ---------------------------------------------------------------------------
__global__ void gcn_agg2(const int* __restrict__ rowptr,
                         const float2* __restrict__ edge,
                         const __half2* __restrict__ h,   // h2 fp16
                         const float* __restrict__ dinv,
                         const float* __restrict__ b,     // b2
                         float* __restrict__ out, int n) {
    constexpr int LQ = D_OUT / 4;            // 8 float2 per row
    int warp = (blockIdx.x * blockDim.x + threadIdx.x) >> 5;
    int lane = threadIdx.x & 31;
    if (warp >= n) return;

    int r0 = rowptr[warp];
    int r1 = rowptr[warp + 1];
    int g = lane >> 3;                       // group 0..3
    int t = lane & 7;                        // sub-lane (all active)

    const float2* h4 = (const float2*)h;
    float4 a0 = {0.f,0.f,0.f,0.f}, a1 = {0.f,0.f,0.f,0.f};

    for (int idx = r0 + g; idx < r1; idx += 8) {
        float2 er = edge[idx];
        {
            float2 raw = h4[(size_t)__float_as_int(er.x) * LQ + t];
            float2 p0 = __half22float2(*(const __half2*)&raw.x);
            float2 p1 = __half22float2(*(const __half2*)&raw.y);
            a0.x += er.y * p0.x; a0.y += er.y * p0.y;
            a0.z += er.y * p1.x; a0.w += er.y * p1.y;
        }
        int idx2 = idx + 4;
        if (idx2 < r1) {
            float2 er2 = edge[idx2];
            float2 raw = h4[(size_t)__float_as_int(er2.x) * LQ + t];
            float2 p0 = __half22float2(*(const __half2*)&raw.x);
            float2 p1 = __half22float2(*(const __half2*)&raw.y);
            a1.x += er2.y * p0.x; a1.y += er2.y * p0.y;
            a1.z += er2.y * p1.x; a1.w += er2.y * p1.y;
        }
    }
    float4 A;
    A.x = a0.x + a1.x; A.y = a0.y + a1.y;
    A.z = a0.z + a1.z; A.w = a0.w + a1.w;
    #pragma unroll
    for (int o = 8; o <= 16; o <<= 1) {
        A.x += __shfl_xor_sync(0xffffffffu, A.x, o);
        A.y += __shfl_xor_sync(0xffffffffu, A.y, o);
        A.z += __shfl_xor_sync(0xffffffffu, A.z, o);
        A.w += __shfl_xor_sync(0xffffffffu, A.w, o);
    }

    if (g == 0) {
        float di = dinv[warp];
        float2 raw = h4[(size_t)warp * LQ + t];
        float2 p0 = __half22float2(*(const __half2*)&raw.x);
        float2 p1 = __half22float2(*(const __half2*)&raw.y);
        float4 bb = ((const float4*)b)[t];
        float4 o;
        o.x = di * A.x + di * di * p0.x + bb.x;
        o.y = di * A.y + di * di * p0.y + bb.y;
        o.z = di * A.z + di * di * p1.x + bb.z;
        o.w = di * A.w + di * di * p1.y + bb.w;
        ((float4*)out)[(size_t)warp * LQ + t] = o;
    }
}

// ---------------------------------------------------------------------------
extern "C" void kernel_launch(void* const* d_in, const int* in_sizes, int n_in,
                              void* d_out, int out_size) {
    const float* x  = (const float*)d_in[0];
    const void*  ei = d_in[1];
    const float* ew = (const float*)d_in[2];
    const float* W1 = (const float*)d_in[3];
    const float* b1 = (const float*)d_in[4];
    const float* W2 = (const float*)d_in[5];
    const float* b2 = (const float*)d_in[6];
    float*       out = (float*)d_out;

    int n = in_sizes[0] / D_IN;      // 100000
    int E = in_sizes[2];             // 1600000
    int nb = (n + 255) / 256;        // 391

    __half2 *h1h, *h2h;
    unsigned long long* pack;
    float* deg;
    int *row, *flag;
    unsigned* pos32;
    float2* edge;
    cudaGetSymbolAddress((void**)&pack,  s_pack);
    cudaGetSymbolAddress((void**)&h1h,   s_h1h);
    cudaGetSymbolAddress((void**)&h2h,   s_h2h);
    cudaGetSymbolAddress((void**)&deg,   s_deg);
    cudaGetSymbolAddress((void**)&row,   s_row);
    cudaGetSymbolAddress((void**)&pos32, s_pos);
    cudaGetSymbolAddress((void**)&edge,  s_edge);
    cudaGetSymbolAddress((void**)&flag,  s_flag);
    unsigned long long* scstate = pack + MAX_N;

    // One-time host resources (no device memory)
    static cudaStream_t st2 = nullptr;
    static cudaEvent_t  evFork = nullptr, evDet = nullptr, evJoin = nullptr;
    if (st2 == nullptr) {
        cudaStreamCreateWithFlags(&st2, cudaStreamNonBlocking);
        cudaEventCreateWithFlags(&evFork, cudaEventDisableTiming);
        cudaEventCreateWithFlags(&evDet,  cudaEventDisableTiming);
        cudaEventCreateWithFlags(&evJoin, cudaEventDisableTiming);
    }

    // ---- side stream: zero+detect, then GEMM1 ----
    cudaEventRecord(evFork, 0);
    cudaStreamWaitEvent(st2, evFork, 0);
    gcn_zdet<<<394, 256, 0, st2>>>((const unsigned*)ei, pack, flag);
    cudaEventRecord(evDet, st2);
    gcn_gemm1<D_IN, D_HID, 64, 32, 4, 6><<<(n + 63) / 64, 128, 0, st2>>>(x, W1, h1h, n);
    cudaEventRecord(evJoin, st2);

    // ---- main chain ----
    cudaStreamWaitEvent(0, evDet, 0);
    gcn_prep<<<2048, 256>>>(ei, ew, flag, pack, pos32, n, E);
    scan_lookback<<<nb, 256>>>(pack, scstate, row, deg, n, E);
    gcn_build<<<(E + 255) / 256, 256>>>(ei, ew, flag, deg, row, pos32, edge, n, E);

    // ---- join: fused agg1+gemm2, then agg2 ----
    cudaStreamWaitEvent(0, evJoin, 0);
    gcn_agg1_gemm2<<<(n * 32 + 511) / 512, 512>>>(row, edge, h1h, deg, b1, W2, h2h, n);
    gcn_agg2<<<(n * 32 + 511) / 512, 512>>>(row, edge, h2h, deg, b2, out, n);
}